// round 12
// baseline (speedup 1.0000x reference)
#include <cuda_runtime.h>
#include <cuda_fp16.h>
#include <math.h>
#include <stdint.h>

// ---------------------------------------------------------------------------
// Problem constants
// ---------------------------------------------------------------------------
#define NTOK  16384
#define DIN   2048
#define HMID  4096
#define NEXP  64
#define NSHARED 8
#define TOPK  2

#define LIMB_SCALE 2048.0f
#define LIMB_INV   (1.0f / 2048.0f)

// Output layout (flattened concat of the reference tuple)
#define G_OFF  0
#define LW_OFF (NTOK * NSHARED)
#define LI_OFF (LW_OFF + NTOK * TOPK)
#define W_OFF  (LI_OFF + NTOK * TOPK)

// ---------------------------------------------------------------------------
// Scratch (static device arrays; no allocation). All *1 (residual) planes are
// stored pre-scaled by 2^11 so fp16-accumulate corrections stay in normal
// fp16 range; consumers multiply by 2^-11 when folding into fp32.
// ---------------------------------------------------------------------------
__device__ __half g_x0[(size_t)NTOK * DIN];
__device__ __half g_x1[(size_t)NTOK * DIN];           // scaled 2^11
__device__ __half g_w0[(size_t)HMID * DIN];
__device__ __half g_w1[(size_t)HMID * DIN];           // scaled 2^11
__device__ __half g_h0[(size_t)NTOK * HMID];
__device__ __half g_h1[(size_t)NTOK * HMID];          // scaled 2^11
__device__ __half g_u0[(size_t)NEXP * HMID];
__device__ __half g_u1[(size_t)NEXP * HMID];          // scaled 2^11

#define KSPLIT 4
#define RK (HMID / KSPLIT)                            // 1024
__device__ float g_part[KSPLIT][NTOK][NEXP];          // partial logits

__device__ __forceinline__ uint32_t smem_u32(const void* p) {
    uint32_t a;
    asm("{ .reg .u64 t; cvta.to.shared.u64 t, %1; cvt.u32.u64 %0, t; }"
        : "=r"(a) : "l"(p));
    return a;
}

__device__ __forceinline__ float gelu_exact(float v) {
    return 0.5f * v * (1.0f + erff(v * 0.70710678118654752440f));
}

__device__ __forceinline__ void ldsm_x4(uint32_t* r, uint32_t addr) {
    asm volatile("ldmatrix.sync.aligned.m8n8.x4.shared.b16 {%0,%1,%2,%3}, [%4];"
                 : "=r"(r[0]), "=r"(r[1]), "=r"(r[2]), "=r"(r[3]) : "r"(addr));
}

// fp32-accumulate MMA (main product)
__device__ __forceinline__ void mma16816(float* d, const uint32_t* a,
                                         uint32_t b0, uint32_t b1) {
    asm volatile(
        "mma.sync.aligned.m16n8k16.row.col.f32.f16.f16.f32 "
        "{%0,%1,%2,%3}, {%4,%5,%6,%7}, {%8,%9}, {%0,%1,%2,%3};"
        : "+f"(d[0]), "+f"(d[1]), "+f"(d[2]), "+f"(d[3])
        : "r"(a[0]), "r"(a[1]), "r"(a[2]), "r"(a[3]), "r"(b0), "r"(b1));
}

// fp16-accumulate MMA (correction products; D,C are 2 regs of half2)
__device__ __forceinline__ void mma16816_h(uint32_t* d, const uint32_t* a,
                                           uint32_t b0, uint32_t b1) {
    asm volatile(
        "mma.sync.aligned.m16n8k16.row.col.f16.f16.f16.f16 "
        "{%0,%1}, {%2,%3,%4,%5}, {%6,%7}, {%0,%1};"
        : "+r"(d[0]), "+r"(d[1])
        : "r"(a[0]), "r"(a[1]), "r"(a[2]), "r"(a[3]), "r"(b0), "r"(b1));
}

__device__ __forceinline__ void fold_corr(float* acc, const uint32_t* t) {
    __half2 h0 = *reinterpret_cast<const __half2*>(&t[0]);
    __half2 h1 = *reinterpret_cast<const __half2*>(&t[1]);
    float2 f0 = __half22float2(h0);
    float2 f1 = __half22float2(h1);
    acc[0] = fmaf(f0.x, LIMB_INV, acc[0]);
    acc[1] = fmaf(f0.y, LIMB_INV, acc[1]);
    acc[2] = fmaf(f1.x, LIMB_INV, acc[2]);
    acc[3] = fmaf(f1.y, LIMB_INV, acc[3]);
}

#define CP_ASYNC16(dst, src) \
    asm volatile("cp.async.cg.shared.global [%0], [%1], 16;" \
                 :: "r"(dst), "l"(src) : "memory")
#define CP_COMMIT() asm volatile("cp.async.commit_group;" ::: "memory")
#define BAR_SYNC(id, cnt) \
    asm volatile("bar.sync %0, %1;" :: "r"(id), "r"(cnt) : "memory")
#define BAR_ARRIVE(id, cnt) \
    asm volatile("bar.arrive %0, %1;" :: "r"(id), "r"(cnt) : "memory")

// ---------------------------------------------------------------------------
// conv_x: split x into fp16 limb planes; residual plane scaled by 2^11
// ---------------------------------------------------------------------------
__global__ void __launch_bounds__(256)
conv_x_kernel(const float* __restrict__ x) {
    size_t i = ((size_t)blockIdx.x * 256 + threadIdx.x) * 4;
    float4 v = *reinterpret_cast<const float4*>(&x[i]);
    float a[4] = {v.x, v.y, v.z, v.w};
    unsigned short u0[4], u1[4];
#pragma unroll
    for (int j = 0; j < 4; j++) {
        __half h0 = __float2half_rn(a[j]);
        float r = (a[j] - __half2float(h0)) * LIMB_SCALE;
        u0[j] = __half_as_ushort(h0);
        u1[j] = __half_as_ushort(__float2half_rn(r));
    }
    *reinterpret_cast<uint2*>(&g_x0[i]) =
        make_uint2((uint32_t)u0[0] | ((uint32_t)u0[1] << 16),
                   (uint32_t)u0[2] | ((uint32_t)u0[3] << 16));
    *reinterpret_cast<uint2*>(&g_x1[i]) =
        make_uint2((uint32_t)u1[0] | ((uint32_t)u1[1] << 16),
                   (uint32_t)u1[2] | ((uint32_t)u1[3] << 16));
}

// ---------------------------------------------------------------------------
// conv_w1: transpose W1 [K,N] -> [N,K]; residual plane scaled by 2^11
// ---------------------------------------------------------------------------
__global__ void __launch_bounds__(256)
conv_w1_kernel(const float* __restrict__ W1) {
    __shared__ float tile[32][33];
    const int tx = threadIdx.x, ty = threadIdx.y;
    const int n0 = blockIdx.x * 32;
    const int k0 = blockIdx.y * 32;
#pragma unroll
    for (int j = 0; j < 4; j++)
        tile[ty + j * 8][tx] = W1[(size_t)(k0 + ty + j * 8) * HMID + n0 + tx];
    __syncthreads();
#pragma unroll
    for (int j = 0; j < 4; j++) {
        float v = tile[tx][ty + j * 8];
        __half h0 = __float2half_rn(v);
        float r = (v - __half2float(h0)) * LIMB_SCALE;
        size_t o = (size_t)(n0 + ty + j * 8) * DIN + k0 + tx;
        g_w0[o] = h0;
        g_w1[o] = __float2half_rn(r);
    }
}

// ---------------------------------------------------------------------------
// conv_w2: transpose W2 -> [64][4096]; residual plane scaled by 2^11
// ---------------------------------------------------------------------------
__global__ void __launch_bounds__(256)
conv_w2_kernel(const float* __restrict__ W2) {
    __shared__ float tile[32][33];
    const int tx = threadIdx.x, ty = threadIdx.y;
    const int n0 = blockIdx.x * 32;
    const int k0 = blockIdx.y * 32;
#pragma unroll
    for (int j = 0; j < 4; j++)
        tile[ty + j * 8][tx] = W2[(size_t)(k0 + ty + j * 8) * NEXP + n0 + tx];
    __syncthreads();
#pragma unroll
    for (int j = 0; j < 4; j++) {
        float v = tile[tx][ty + j * 8];
        __half h0 = __float2half_rn(v);
        float r = (v - __half2float(h0)) * LIMB_SCALE;
        size_t o = (size_t)(n0 + ty + j * 8) * HMID + k0 + tx;
        g_u0[o] = h0;
        g_u1[o] = __float2half_rn(r);
    }
}

// ---------------------------------------------------------------------------
// gemm1: h = gelu(x @ W1 + b1). Main product fp32-acc; corrections
// (x0·w1' + x1'·w0, limbs pre-scaled 2^11) via fp16-acc MMA, folded into the
// fp32 accumulators once per k16 with a 2^-11 FMA. Named-barrier pipeline
// from R11 (ready/free families).
// ---------------------------------------------------------------------------
#define TILE64  (128 * 64)
#define STAGE64 (4 * TILE64)
#define GSTAGES 3
#define SMEM_GEMM (GSTAGES * STAGE64)  // 98304
#define KT (DIN / 32)                  // 64

__global__ void __launch_bounds__(256, 2)
gemm1_hmma_kernel(const float* __restrict__ b1) {
    extern __shared__ char smem[];
    const uint32_t sbase = smem_u32(smem);
    const int tid = threadIdx.x;
    const int wid = tid >> 5;
    const int lid = tid & 31;
    const int row0 = blockIdx.y * 128;
    const int col0 = blockIdx.x * 128;
    const int wm = (wid >> 2) * 64;
    const int wn = (wid & 3) * 32;

    const int lr = tid >> 1;
    const int cc = (tid & 1) * 2;
    const int mS = (lr >> 1) & 3;
    const uint32_t dst0 = (uint32_t)lr * 64 + (uint32_t)(((cc)     ^ mS) << 4);
    const uint32_t dst1 = (uint32_t)lr * 64 + (uint32_t)(((cc + 1) ^ mS) << 4);
    const char* gA0 = (const char*)(g_x0 + (size_t)(row0 + lr) * DIN) + cc * 16;
    const char* gA1 = (const char*)(g_x1 + (size_t)(row0 + lr) * DIN) + cc * 16;
    const char* gB0 = (const char*)(g_w0 + (size_t)(col0 + lr) * DIN) + cc * 16;
    const char* gB1 = (const char*)(g_w1 + (size_t)(col0 + lr) * DIN) + cc * 16;

    float acc[4][4][4];
#pragma unroll
    for (int i = 0; i < 4; i++)
#pragma unroll
        for (int j = 0; j < 4; j++)
#pragma unroll
            for (int k = 0; k < 4; k++) acc[i][j][k] = 0.f;

    auto load_stage = [&](int s, int kt) {
        const uint32_t sb = sbase + s * STAGE64;
        const int go = kt * 64;
        CP_ASYNC16(sb + dst0,              gA0 + go);
        CP_ASYNC16(sb + dst1,              gA0 + go + 16);
        CP_ASYNC16(sb + TILE64 + dst0,     gA1 + go);
        CP_ASYNC16(sb + TILE64 + dst1,     gA1 + go + 16);
        CP_ASYNC16(sb + 2 * TILE64 + dst0, gB0 + go);
        CP_ASYNC16(sb + 2 * TILE64 + dst1, gB0 + go + 16);
        CP_ASYNC16(sb + 3 * TILE64 + dst0, gB1 + go);
        CP_ASYNC16(sb + 3 * TILE64 + dst1, gB1 + go + 16);
        CP_COMMIT();
    };

    const uint32_t aRowB = (uint32_t)(wm + (lid & 15)) * 64;
    const int cidxA = lid >> 4;
    const int mA = ((lid & 15) >> 1) & 3;
    const int brow = (lid & 7) + ((lid >> 4) & 1) * 8;
    const uint32_t bRowB = (uint32_t)(wn + brow) * 64;
    const int cidxB = (lid >> 3) & 1;
    const int mB = (brow >> 1) & 3;
    uint32_t aCol[2], bCol[2];
#pragma unroll
    for (int k16 = 0; k16 < 2; k16++) {
        aCol[k16] = (uint32_t)((((k16 << 1) | cidxA) ^ mA) << 4);
        bCol[k16] = (uint32_t)((((k16 << 1) | cidxB) ^ mB) << 4);
    }

    load_stage(0, 0);
    load_stage(1, 1);
    asm volatile("cp.async.wait_group 1;" ::: "memory");
    BAR_ARRIVE(1 + 0, 512);                  // ready[0] only

    int r0 = 0, r1 = 1, r2 = 2;

    for (int kt = 0; kt < KT; kt++) {
        BAR_SYNC(1 + r0, 512);

        const uint32_t sb = sbase + r0 * STAGE64;

#pragma unroll
        for (int k16 = 0; k16 < 2; k16++) {
            uint32_t b0[2][4], b1f[2][4];
#pragma unroll
            for (int nt2 = 0; nt2 < 2; nt2++) {
                const uint32_t bo = bRowB + nt2 * 1024 + bCol[k16];
                ldsm_x4(b0[nt2],  sb + 2 * TILE64 + bo);
                ldsm_x4(b1f[nt2], sb + 3 * TILE64 + bo);
            }
            uint32_t a0[4][4];
#pragma unroll
            for (int mt = 0; mt < 4; mt++)
                ldsm_x4(a0[mt], sb + aRowB + mt * 1024 + aCol[k16]);

            // ---- main product: fp32 accumulate ----
#pragma unroll
            for (int mt = 0; mt < 4; mt++)
#pragma unroll
                for (int nt = 0; nt < 4; nt++) {
                    const int n2 = nt >> 1, h = (nt & 1) * 2;
                    mma16816(acc[mt][nt], a0[mt], b0[n2][h], b0[n2][h + 1]);
                }

            // ---- corrections: fp16 accumulate, per-mt transient a1 ----
#pragma unroll
            for (int mt = 0; mt < 4; mt++) {
                uint32_t a1[4];
                ldsm_x4(a1, sb + TILE64 + aRowB + mt * 1024 + aCol[k16]);
                uint32_t t[4][2];
#pragma unroll
                for (int nt = 0; nt < 4; nt++) {
                    const int n2 = nt >> 1, h = (nt & 1) * 2;
                    t[nt][0] = 0u; t[nt][1] = 0u;
                    mma16816_h(t[nt], a0[mt], b1f[n2][h], b1f[n2][h + 1]);
                }
#pragma unroll
                for (int nt = 0; nt < 4; nt++) {
                    const int n2 = nt >> 1, h = (nt & 1) * 2;
                    mma16816_h(t[nt], a1, b0[n2][h], b0[n2][h + 1]);
                }
#pragma unroll
                for (int nt = 0; nt < 4; nt++)
                    fold_corr(acc[mt][nt], t[nt]);
            }

            if (k16 == 1) {
                // all stage-kt reads done -> release; fill stage kt+2
                if (kt + 3 < KT) BAR_ARRIVE(4 + r0, 512);
                if (kt >= 1 && kt + 2 < KT) BAR_SYNC(4 + r2, 512);
                if (kt + 2 < KT) load_stage(r2, kt + 2);
                if (kt + 1 < KT) {
                    if (kt + 2 < KT) {
                        asm volatile("cp.async.wait_group 1;" ::: "memory");
                    } else {
                        asm volatile("cp.async.wait_group 0;" ::: "memory");
                    }
                    BAR_ARRIVE(1 + r1, 512);
                }
            }
        }

        const int t = r0; r0 = r1; r1 = r2; r2 = t;
    }

    // epilogue: bias + gelu + split into limb planes (residual scaled 2^11)
    const int g = lid >> 2;
    const int i2 = (lid & 3) * 2;
#pragma unroll
    for (int nt = 0; nt < 4; nt++) {
        const int col = col0 + wn + nt * 8 + i2;
        const float bx = b1[col], by = b1[col + 1];
#pragma unroll
        for (int mt = 0; mt < 4; mt++) {
            const int row = row0 + wm + mt * 16 + g;
            float hv[4];
            hv[0] = gelu_exact(acc[mt][nt][0] + bx);
            hv[1] = gelu_exact(acc[mt][nt][1] + by);
            hv[2] = gelu_exact(acc[mt][nt][2] + bx);
            hv[3] = gelu_exact(acc[mt][nt][3] + by);
            unsigned short p[4], q[4];
#pragma unroll
            for (int j = 0; j < 4; j++) {
                __half h0 = __float2half_rn(hv[j]);
                float r = (hv[j] - __half2float(h0)) * LIMB_SCALE;
                p[j] = __half_as_ushort(h0);
                q[j] = __half_as_ushort(__float2half_rn(r));
            }
            size_t o0 = (size_t)row * HMID + col;
            size_t o1 = (size_t)(row + 8) * HMID + col;
            *reinterpret_cast<uint32_t*>(&g_h0[o0]) =
                (uint32_t)p[0] | ((uint32_t)p[1] << 16);
            *reinterpret_cast<uint32_t*>(&g_h0[o1]) =
                (uint32_t)p[2] | ((uint32_t)p[3] << 16);
            *reinterpret_cast<uint32_t*>(&g_h1[o0]) =
                (uint32_t)q[0] | ((uint32_t)q[1] << 16);
            *reinterpret_cast<uint32_t*>(&g_h1[o1]) =
                (uint32_t)q[2] | ((uint32_t)q[3] << 16);
        }
    }
}

// ---------------------------------------------------------------------------
// router_partial: partial logits over a K-slice of 1024, same limb scheme.
// ---------------------------------------------------------------------------
#define ROWB 80
#define R_ATILE (128 * ROWB)
#define R_BTILE (64 * ROWB)
#define R_STAGE (2 * R_ATILE + 2 * R_BTILE)  // 30720
#define R_NSTAGE 3
#define R_KT (RK / 32)                       // 32
#define SMEM_RPART (R_NSTAGE * R_STAGE)      // 92160

__global__ void __launch_bounds__(256, 2)
router_partial_kernel() {
    extern __shared__ char smem[];
    const uint32_t sbase = smem_u32(smem);

    const int tid = threadIdx.x;
    const int wid = tid >> 5;
    const int lid = tid & 31;
    const int tok0 = blockIdx.x * 128;
    const int ks = blockIdx.y;
    const int wm = (wid >> 1) * 32;
    const int wn = (wid & 1) * 32;

    const int lr  = tid >> 1;
    const int cc  = (tid & 1) * 2;
    const char* gA0 = (const char*)(g_h0 + (size_t)(tok0 + lr) * HMID + (size_t)ks * RK) + cc * 16;
    const char* gA1 = (const char*)(g_h1 + (size_t)(tok0 + lr) * HMID + (size_t)ks * RK) + cc * 16;
    const uint32_t sA = (uint32_t)lr * ROWB + cc * 16;
    const int br = tid >> 2;
    const int bc = tid & 3;
    const char* gB0 = (const char*)(g_u0 + (size_t)br * HMID + (size_t)ks * RK) + bc * 16;
    const char* gB1 = (const char*)(g_u1 + (size_t)br * HMID + (size_t)ks * RK) + bc * 16;
    const uint32_t sB = (uint32_t)br * ROWB + bc * 16;

    float acc[2][4][4];
#pragma unroll
    for (int i = 0; i < 2; i++)
#pragma unroll
        for (int j = 0; j < 4; j++)
#pragma unroll
            for (int k = 0; k < 4; k++) acc[i][j][k] = 0.f;

    auto load_stage = [&](int s, int kt) {
        const uint32_t sb = sbase + s * R_STAGE;
        const int go = kt * 64;
        CP_ASYNC16(sb + sA,      gA0 + go);
        CP_ASYNC16(sb + sA + 16, gA0 + go + 16);
        CP_ASYNC16(sb + R_ATILE + sA,      gA1 + go);
        CP_ASYNC16(sb + R_ATILE + sA + 16, gA1 + go + 16);
        CP_ASYNC16(sb + 2 * R_ATILE + sB,           gB0 + go);
        CP_ASYNC16(sb + 2 * R_ATILE + R_BTILE + sB, gB1 + go);
        CP_COMMIT();
    };

    const uint32_t aRow = (uint32_t)(wm + (lid & 15)) * ROWB + (lid >> 4) * 16;
    const uint32_t bRow = (uint32_t)(wn + (lid & 7) + ((lid >> 4) & 1) * 8) * ROWB
                        + ((lid >> 3) & 1) * 16;

    load_stage(0, 0);
    load_stage(1, 1);

    for (int kt = 0; kt < R_KT; kt++) {
        if (kt < R_KT - 1) {
            asm volatile("cp.async.wait_group 1;" ::: "memory");
        } else {
            asm volatile("cp.async.wait_group 0;" ::: "memory");
        }
        __syncthreads();

        const uint32_t sb = sbase + (kt % R_NSTAGE) * R_STAGE;
#pragma unroll
        for (int k16 = 0; k16 < 2; k16++) {
            const uint32_t kOff = k16 * 32;
            uint32_t b0[2][4], b1f[2][4];
#pragma unroll
            for (int nt2 = 0; nt2 < 2; nt2++) {
                ldsm_x4(b0[nt2],  sb + 2 * R_ATILE + bRow + kOff + nt2 * 16 * ROWB);
                ldsm_x4(b1f[nt2], sb + 2 * R_ATILE + R_BTILE + bRow + kOff + nt2 * 16 * ROWB);
            }
            uint32_t a0[2][4];
#pragma unroll
            for (int mt = 0; mt < 2; mt++)
                ldsm_x4(a0[mt], sb + aRow + kOff + mt * 16 * ROWB);

#pragma unroll
            for (int mt = 0; mt < 2; mt++)
#pragma unroll
                for (int nt = 0; nt < 4; nt++) {
                    const int n2 = nt >> 1, h = (nt & 1) * 2;
                    mma16816(acc[mt][nt], a0[mt], b0[n2][h], b0[n2][h + 1]);
                }
            if (k16 == 0 && kt + 2 < R_KT)
                load_stage((kt + 2) % R_NSTAGE, kt + 2);

#pragma unroll
            for (int mt = 0; mt < 2; mt++) {
                uint32_t a1[4];
                ldsm_x4(a1, sb + R_ATILE + aRow + kOff + mt * 16 * ROWB);
                uint32_t t[4][2];
#pragma unroll
                for (int nt = 0; nt < 4; nt++) {
                    const int n2 = nt >> 1, h = (nt & 1) * 2;
                    t[nt][0] = 0u; t[nt][1] = 0u;
                    mma16816_h(t[nt], a0[mt], b1f[n2][h], b1f[n2][h + 1]);
                }
#pragma unroll
                for (int nt = 0; nt < 4; nt++) {
                    const int n2 = nt >> 1, h = (nt & 1) * 2;
                    mma16816_h(t[nt], a1, b0[n2][h], b0[n2][h + 1]);
                }
#pragma unroll
                for (int nt = 0; nt < 4; nt++)
                    fold_corr(acc[mt][nt], t[nt]);
            }
        }
    }

    const int g = lid >> 2;
    const int i2 = (lid & 3) * 2;
#pragma unroll
    for (int nt = 0; nt < 4; nt++) {
        const int col = wn + nt * 8 + i2;
#pragma unroll
        for (int mt = 0; mt < 2; mt++) {
            const int row = wm + mt * 16 + g;
            *reinterpret_cast<float2*>(&g_part[ks][tok0 + row][col]) =
                make_float2(acc[mt][nt][0], acc[mt][nt][1]);
            *reinterpret_cast<float2*>(&g_part[ks][tok0 + row + 8][col]) =
                make_float2(acc[mt][nt][2], acc[mt][nt][3]);
        }
    }
}

// ---------------------------------------------------------------------------
// router_finalize: sum KSPLIT partials + b2, softmax, split, top-2, outputs.
// ---------------------------------------------------------------------------
#define LGS 68
#define SMEM_RFIN (128 * LGS * 4 + 512)

__global__ void __launch_bounds__(256)
router_finalize_kernel(const float* __restrict__ b2, float* __restrict__ out) {
    extern __shared__ float rs[];
    float* lg   = rs;
    float* sinv = rs + 128 * LGS;

    const int tid = threadIdx.x;
    const int tok0 = blockIdx.x * 128;

#pragma unroll
    for (int hh = 0; hh < 8; hh++) {
        int f = tid + 256 * hh;
        int row = f >> 4;
        int c4 = (f & 15) * 4;
        float4 s = *reinterpret_cast<const float4*>(&g_part[0][tok0 + row][c4]);
#pragma unroll
        for (int ks = 1; ks < KSPLIT; ks++) {
            float4 p = *reinterpret_cast<const float4*>(&g_part[ks][tok0 + row][c4]);
            s.x += p.x; s.y += p.y; s.z += p.z; s.w += p.w;
        }
        float4 bb = *reinterpret_cast<const float4*>(&b2[c4]);
        s.x += bb.x; s.y += bb.y; s.z += bb.z; s.w += bb.w;
        *reinterpret_cast<float4*>(&lg[row * LGS + c4]) = s;
    }
    __syncthreads();

    if (tid < 128) {
        const int tok = tok0 + tid;
        float* row = &lg[tid * LGS];
        float mx = -1e30f;
#pragma unroll
        for (int e = 0; e < NEXP; e++) mx = fmaxf(mx, row[e]);
        float s = 0.f;
#pragma unroll
        for (int e = 0; e < NEXP; e++) {
            float ev = expf(row[e] - mx);
            row[e] = ev;
            s += ev;
        }
        float inv = 1.0f / s;
        sinv[tid] = inv;

        float v1 = -1.0f, v2 = -1.0f;
        int i1 = 0, i2v = 0;
#pragma unroll
        for (int e = NSHARED; e < NEXP; e++) {
            float v = row[e];
            if (v > v1)      { v2 = v1; i2v = i1; v1 = v; i1 = e; }
            else if (v > v2) { v2 = v;  i2v = e; }
        }
#pragma unroll
        for (int e = 0; e < NSHARED; e++)
            out[G_OFF + (size_t)tok * NSHARED + e] = row[e] * inv;
        out[LW_OFF + (size_t)tok * TOPK + 0] = v1 * inv;
        out[LW_OFF + (size_t)tok * TOPK + 1] = v2 * inv;
        out[LI_OFF + (size_t)tok * TOPK + 0] = (float)(i1 - NSHARED);
        out[LI_OFF + (size_t)tok * TOPK + 1] = (float)(i2v - NSHARED);
    }
    __syncthreads();

#pragma unroll
    for (int hh = 0; hh < 16; hh++) {
        int f = tid + 256 * hh;
        int tr = f >> 5;
        int ec = (f & 31) * 2;
        float inv = sinv[tr];
        float2 v = *reinterpret_cast<const float2*>(&lg[tr * LGS + ec]);
        v.x *= inv; v.y *= inv;
        *reinterpret_cast<float2*>(
            &out[W_OFF + (size_t)(tok0 + tr) * NEXP + ec]) = v;
    }
}

// ---------------------------------------------------------------------------
extern "C" void kernel_launch(void* const* d_in, const int* in_sizes, int n_in,
                              void* d_out, int out_size) {
    const float* x  = (const float*)d_in[0];
    const float* W1 = (const float*)d_in[1];
    const float* b1 = (const float*)d_in[2];
    const float* W2 = (const float*)d_in[3];
    const float* b2 = (const float*)d_in[4];
    float* out = (float*)d_out;

    static int attr_done = 0;
    if (!attr_done) {
        cudaFuncSetAttribute(gemm1_hmma_kernel,
                             cudaFuncAttributeMaxDynamicSharedMemorySize, SMEM_GEMM);
        cudaFuncSetAttribute(router_partial_kernel,
                             cudaFuncAttributeMaxDynamicSharedMemorySize, SMEM_RPART);
        cudaFuncSetAttribute(router_finalize_kernel,
                             cudaFuncAttributeMaxDynamicSharedMemorySize, SMEM_RFIN);
        attr_done = 1;
    }

    conv_x_kernel<<<(NTOK * DIN) / (256 * 4), 256>>>(x);
    conv_w1_kernel<<<dim3(HMID / 32, DIN / 32), dim3(32, 8)>>>(W1);
    conv_w2_kernel<<<dim3(NEXP / 32, HMID / 32), dim3(32, 8)>>>(W2);
    gemm1_hmma_kernel<<<dim3(HMID / 128, NTOK / 128), 256, SMEM_GEMM>>>(b1);
    router_partial_kernel<<<dim3(NTOK / 128, KSPLIT), 256, SMEM_RPART>>>();
    router_finalize_kernel<<<NTOK / 128, 256, SMEM_RFIN>>>(b2, out);
}

// round 13
// speedup vs baseline: 1.1882x; 1.1882x over previous
#include <cuda_runtime.h>
#include <cuda_fp16.h>
#include <math.h>
#include <stdint.h>

// ---------------------------------------------------------------------------
// Problem constants
// ---------------------------------------------------------------------------
#define NTOK  16384
#define DIN   2048
#define HMID  4096
#define NEXP  64
#define NSHARED 8
#define TOPK  2

// Output layout (flattened concat of the reference tuple)
#define G_OFF  0
#define LW_OFF (NTOK * NSHARED)
#define LI_OFF (LW_OFF + NTOK * TOPK)
#define W_OFF  (LI_OFF + NTOK * TOPK)

// ---------------------------------------------------------------------------
// Scratch (static device arrays; no allocation)
// ---------------------------------------------------------------------------
__device__ __half g_x0[(size_t)NTOK * DIN];           // x limb planes
__device__ __half g_x1[(size_t)NTOK * DIN];
__device__ __half g_w0[(size_t)HMID * DIN];           // W1^T limb planes
__device__ __half g_w1[(size_t)HMID * DIN];
__device__ __half g_h0[(size_t)NTOK * HMID];          // h limb planes
__device__ __half g_h1[(size_t)NTOK * HMID];
__device__ __half g_u0[(size_t)NEXP * HMID];          // W2^T limb planes
__device__ __half g_u1[(size_t)NEXP * HMID];

#define KSPLIT 4
#define RK (HMID / KSPLIT)                            // 1024
__device__ float g_part[KSPLIT][NTOK][NEXP];          // partial logits

__device__ __forceinline__ uint32_t smem_u32(const void* p) {
    uint32_t a;
    asm("{ .reg .u64 t; cvta.to.shared.u64 t, %1; cvt.u32.u64 %0, t; }"
        : "=r"(a) : "l"(p));
    return a;
}

__device__ __forceinline__ float gelu_exact(float v) {
    return 0.5f * v * (1.0f + erff(v * 0.70710678118654752440f));
}

__device__ __forceinline__ void ldsm_x4(uint32_t* r, uint32_t addr) {
    asm volatile("ldmatrix.sync.aligned.m8n8.x4.shared.b16 {%0,%1,%2,%3}, [%4];"
                 : "=r"(r[0]), "=r"(r[1]), "=r"(r[2]), "=r"(r[3]) : "r"(addr));
}

__device__ __forceinline__ void mma16816(float* d, const uint32_t* a,
                                         uint32_t b0, uint32_t b1) {
    asm volatile(
        "mma.sync.aligned.m16n8k16.row.col.f32.f16.f16.f32 "
        "{%0,%1,%2,%3}, {%4,%5,%6,%7}, {%8,%9}, {%0,%1,%2,%3};"
        : "+f"(d[0]), "+f"(d[1]), "+f"(d[2]), "+f"(d[3])
        : "r"(a[0]), "r"(a[1]), "r"(a[2]), "r"(a[3]), "r"(b0), "r"(b1));
}

#define CP_ASYNC16(dst, src) \
    asm volatile("cp.async.cg.shared.global [%0], [%1], 16;" \
                 :: "r"(dst), "l"(src) : "memory")
#define CP_COMMIT() asm volatile("cp.async.commit_group;" ::: "memory")

__device__ __forceinline__ uint32_t pack_limbs(float x, float y,
                                               float& rx, float& ry) {
    __half hx = __float2half_rn(x), hy = __float2half_rn(y);
    rx = x - __half2float(hx);
    ry = y - __half2float(hy);
    return (uint32_t)__half_as_ushort(hx) | ((uint32_t)__half_as_ushort(hy) << 16);
}

// ---------------------------------------------------------------------------
// conv_x: split x into 2 fp16 limb planes (row-major, K contiguous)
// ---------------------------------------------------------------------------
__global__ void __launch_bounds__(256)
conv_x_kernel(const float* __restrict__ x) {
    size_t i = ((size_t)blockIdx.x * 256 + threadIdx.x) * 4;
    float4 v = *reinterpret_cast<const float4*>(&x[i]);
    float a[4] = {v.x, v.y, v.z, v.w};
    unsigned short u0[4], u1[4];
#pragma unroll
    for (int j = 0; j < 4; j++) {
        __half h0 = __float2half_rn(a[j]);
        float r = a[j] - __half2float(h0);
        u0[j] = __half_as_ushort(h0);
        u1[j] = __half_as_ushort(__float2half_rn(r));
    }
    *reinterpret_cast<uint2*>(&g_x0[i]) =
        make_uint2((uint32_t)u0[0] | ((uint32_t)u0[1] << 16),
                   (uint32_t)u0[2] | ((uint32_t)u0[3] << 16));
    *reinterpret_cast<uint2*>(&g_x1[i]) =
        make_uint2((uint32_t)u1[0] | ((uint32_t)u1[1] << 16),
                   (uint32_t)u1[2] | ((uint32_t)u1[3] << 16));
}

// ---------------------------------------------------------------------------
// conv_w1: transpose W1 [K,N] -> [N,K], split into 2 fp16 limb planes
// ---------------------------------------------------------------------------
__global__ void __launch_bounds__(256)
conv_w1_kernel(const float* __restrict__ W1) {
    __shared__ float tile[32][33];
    const int tx = threadIdx.x, ty = threadIdx.y;
    const int n0 = blockIdx.x * 32;
    const int k0 = blockIdx.y * 32;
#pragma unroll
    for (int j = 0; j < 4; j++)
        tile[ty + j * 8][tx] = W1[(size_t)(k0 + ty + j * 8) * HMID + n0 + tx];
    __syncthreads();
#pragma unroll
    for (int j = 0; j < 4; j++) {
        float v = tile[tx][ty + j * 8];
        __half h0 = __float2half_rn(v);
        float r = v - __half2float(h0);
        size_t o = (size_t)(n0 + ty + j * 8) * DIN + k0 + tx;
        g_w0[o] = h0;
        g_w1[o] = __float2half_rn(r);
    }
}

// ---------------------------------------------------------------------------
// conv_w2: transpose W2 [K=4096, 64] -> [64][4096], split into 2 limb planes
// ---------------------------------------------------------------------------
__global__ void __launch_bounds__(256)
conv_w2_kernel(const float* __restrict__ W2) {
    __shared__ float tile[32][33];
    const int tx = threadIdx.x, ty = threadIdx.y;
    const int n0 = blockIdx.x * 32;
    const int k0 = blockIdx.y * 32;
#pragma unroll
    for (int j = 0; j < 4; j++)
        tile[ty + j * 8][tx] = W2[(size_t)(k0 + ty + j * 8) * NEXP + n0 + tx];
    __syncthreads();
#pragma unroll
    for (int j = 0; j < 4; j++) {
        float v = tile[tx][ty + j * 8];
        __half h0 = __float2half_rn(v);
        float r = v - __half2float(h0);
        size_t o = (size_t)(n0 + ty + j * 8) * HMID + k0 + tx;
        g_u0[o] = h0;
        g_u1[o] = __float2half_rn(r);
    }
}

// ---------------------------------------------------------------------------
// gemm1: h = gelu(x @ W1 + b1), fp16 2-limb, 3 products, fp32 accumulate.
// CTA 128(M) x 64(N), 256 threads, warp tile 32x32 (4M x 2N warps).
// SW64-swizzled 64B rows, 3-stage cp.async pipeline, 3 CTAs/SM target
// (24 KB/stage -> 72 KB/CTA; launch_bounds(256,3) caps regs at 85).
// Math bitwise identical to the 128x128 version (same per-element K order).
// ---------------------------------------------------------------------------
#define G_ATILE (128 * 64)               // 8192 B per A limb
#define G_BTILE (64 * 64)                // 4096 B per B limb
#define G_STAGE (2 * G_ATILE + 2 * G_BTILE)  // 24576
#define G_NSTAGE 3
#define SMEM_GEMM (G_NSTAGE * G_STAGE)   // 73728
#define KT (DIN / 32)                    // 64

__global__ void __launch_bounds__(256, 3)
gemm1_hmma_kernel(const float* __restrict__ b1) {
    extern __shared__ char smem[];
    const uint32_t sbase = smem_u32(smem);
    const int tid = threadIdx.x;
    const int wid = tid >> 5;
    const int lid = tid & 31;
    const int row0 = blockIdx.y * 128;
    const int col0 = blockIdx.x * 64;
    const int wm = (wid >> 1) * 32;      // 4 M groups
    const int wn = (wid & 1) * 32;       // 2 N groups

    // ---- loaders ----
    // A: row lr = tid>>1 (0..127), 2 of 4 16B chunks; SW64 swizzle
    const int lr = tid >> 1;
    const int cc = (tid & 1) * 2;
    const int mS = (lr >> 1) & 3;
    const uint32_t dstA0 = (uint32_t)lr * 64 + (uint32_t)(((cc)     ^ mS) << 4);
    const uint32_t dstA1 = (uint32_t)lr * 64 + (uint32_t)(((cc + 1) ^ mS) << 4);
    const char* gA0 = (const char*)(g_x0 + (size_t)(row0 + lr) * DIN) + cc * 16;
    const char* gA1 = (const char*)(g_x1 + (size_t)(row0 + lr) * DIN) + cc * 16;
    // B: row br = tid>>2 (0..63), 1 of 4 chunks
    const int br = tid >> 2;
    const int bc = tid & 3;
    const uint32_t dstB = (uint32_t)br * 64 +
                          (uint32_t)((bc ^ ((br >> 1) & 3)) << 4);
    const char* gB0 = (const char*)(g_w0 + (size_t)(col0 + br) * DIN) + bc * 16;
    const char* gB1 = (const char*)(g_w1 + (size_t)(col0 + br) * DIN) + bc * 16;

    float acc[2][4][4];
#pragma unroll
    for (int i = 0; i < 2; i++)
#pragma unroll
        for (int j = 0; j < 4; j++)
#pragma unroll
            for (int k = 0; k < 4; k++) acc[i][j][k] = 0.f;

    auto load_stage = [&](int s, int kt) {
        const uint32_t sb = sbase + s * G_STAGE;
        const int go = kt * 64;          // 32 halfs = 64B along K
        CP_ASYNC16(sb + dstA0,               gA0 + go);
        CP_ASYNC16(sb + dstA1,               gA0 + go + 16);
        CP_ASYNC16(sb + G_ATILE + dstA0,     gA1 + go);
        CP_ASYNC16(sb + G_ATILE + dstA1,     gA1 + go + 16);
        CP_ASYNC16(sb + 2 * G_ATILE + dstB,           gB0 + go);
        CP_ASYNC16(sb + 2 * G_ATILE + G_BTILE + dstB, gB1 + go);
        CP_COMMIT();
    };

    // ---- ldmatrix address components ----
    const uint32_t aRowB = (uint32_t)(wm + (lid & 15)) * 64;
    const int cidxA = lid >> 4;
    const int mA = ((lid & 15) >> 1) & 3;
    const int brow = (lid & 7) + ((lid >> 4) & 1) * 8;
    const uint32_t bRowB = (uint32_t)(wn + brow) * 64;
    const int cidxB = (lid >> 3) & 1;
    const int mB = (brow >> 1) & 3;
    uint32_t aCol[2], bCol[2];
#pragma unroll
    for (int k16 = 0; k16 < 2; k16++) {
        aCol[k16] = (uint32_t)((((k16 << 1) | cidxA) ^ mA) << 4);
        bCol[k16] = (uint32_t)((((k16 << 1) | cidxB) ^ mB) << 4);
    }

    load_stage(0, 0);
    load_stage(1, 1);

    for (int kt = 0; kt < KT; kt++) {
        if (kt < KT - 1) {
            asm volatile("cp.async.wait_group 1;" ::: "memory");
        } else {
            asm volatile("cp.async.wait_group 0;" ::: "memory");
        }
        __syncthreads();
        // stage (kt+2)%3 was consumed at kt-1; all reads executed before the
        // barrier above -> safe to refill now (loads lead compute by 2 steps)
        if (kt + 2 < KT) load_stage((kt + 2) % G_NSTAGE, kt + 2);

        const uint32_t sb = sbase + (kt % G_NSTAGE) * G_STAGE;
#pragma unroll
        for (int k16 = 0; k16 < 2; k16++) {
            uint32_t b0[2][4], b1f[2][4];
#pragma unroll
            for (int nt2 = 0; nt2 < 2; nt2++) {
                const uint32_t bo = bRowB + nt2 * 1024 + bCol[k16];
                ldsm_x4(b0[nt2],  sb + 2 * G_ATILE + bo);
                ldsm_x4(b1f[nt2], sb + 2 * G_ATILE + G_BTILE + bo);
            }
            uint32_t a0[2][4], a1[2][4];
#pragma unroll
            for (int mt = 0; mt < 2; mt++)
                ldsm_x4(a0[mt], sb + aRowB + mt * 1024 + aCol[k16]);
#pragma unroll
            for (int mt = 0; mt < 2; mt++)
                ldsm_x4(a1[mt], sb + G_ATILE + aRowB + mt * 1024 + aCol[k16]);

#pragma unroll
            for (int mt = 0; mt < 2; mt++)
#pragma unroll
                for (int nt = 0; nt < 4; nt++) {
                    const int n2 = nt >> 1, h = (nt & 1) * 2;
                    mma16816(acc[mt][nt], a0[mt], b0[n2][h], b0[n2][h + 1]);
                }
#pragma unroll
            for (int mt = 0; mt < 2; mt++)
#pragma unroll
                for (int nt = 0; nt < 4; nt++) {
                    const int n2 = nt >> 1, h = (nt & 1) * 2;
                    mma16816(acc[mt][nt], a0[mt], b1f[n2][h], b1f[n2][h + 1]);
                }
#pragma unroll
            for (int mt = 0; mt < 2; mt++)
#pragma unroll
                for (int nt = 0; nt < 4; nt++) {
                    const int n2 = nt >> 1, h = (nt & 1) * 2;
                    mma16816(acc[mt][nt], a1[mt], b0[n2][h], b0[n2][h + 1]);
                }
        }
    }

    // epilogue: bias + gelu + split into fp16 limbs + store
    const int g = lid >> 2;
    const int i2 = (lid & 3) * 2;
#pragma unroll
    for (int nt = 0; nt < 4; nt++) {
        const int col = col0 + wn + nt * 8 + i2;
        const float bx = b1[col], by = b1[col + 1];
#pragma unroll
        for (int mt = 0; mt < 2; mt++) {
            const int row = row0 + wm + mt * 16 + g;
            float lox = gelu_exact(acc[mt][nt][0] + bx);
            float loy = gelu_exact(acc[mt][nt][1] + by);
            float hix = gelu_exact(acc[mt][nt][2] + bx);
            float hiy = gelu_exact(acc[mt][nt][3] + by);
            float r0, r1, r2, r3;
            uint32_t p0 = pack_limbs(lox, loy, r0, r1);
            uint32_t p1 = pack_limbs(hix, hiy, r2, r3);
            size_t o0 = (size_t)row * HMID + col;
            size_t o1 = (size_t)(row + 8) * HMID + col;
            *reinterpret_cast<uint32_t*>(&g_h0[o0]) = p0;
            *reinterpret_cast<uint32_t*>(&g_h0[o1]) = p1;
            __half q0 = __float2half_rn(r0), q1 = __float2half_rn(r1);
            __half q2 = __float2half_rn(r2), q3 = __float2half_rn(r3);
            *reinterpret_cast<uint32_t*>(&g_h1[o0]) =
                (uint32_t)__half_as_ushort(q0) | ((uint32_t)__half_as_ushort(q1) << 16);
            *reinterpret_cast<uint32_t*>(&g_h1[o1]) =
                (uint32_t)__half_as_ushort(q2) | ((uint32_t)__half_as_ushort(q3) << 16);
        }
    }
}

// ---------------------------------------------------------------------------
// router_partial: partial logits over a K-slice of 1024 (R11 fp32-acc form).
// grid (NTOK/128, KSPLIT), 2 CTAs/SM. Stores raw fp32 partials (no bias).
// ---------------------------------------------------------------------------
#define ROWB 80
#define R_ATILE (128 * ROWB)
#define R_BTILE (64 * ROWB)
#define R_STAGE (2 * R_ATILE + 2 * R_BTILE)  // 30720
#define R_NSTAGE 3
#define R_KT (RK / 32)                       // 32
#define SMEM_RPART (R_NSTAGE * R_STAGE)      // 92160

__global__ void __launch_bounds__(256, 2)
router_partial_kernel() {
    extern __shared__ char smem[];
    const uint32_t sbase = smem_u32(smem);

    const int tid = threadIdx.x;
    const int wid = tid >> 5;
    const int lid = tid & 31;
    const int tok0 = blockIdx.x * 128;
    const int ks = blockIdx.y;
    const int wm = (wid >> 1) * 32;
    const int wn = (wid & 1) * 32;

    const int lr  = tid >> 1;
    const int cc  = (tid & 1) * 2;
    const char* gA0 = (const char*)(g_h0 + (size_t)(tok0 + lr) * HMID + (size_t)ks * RK) + cc * 16;
    const char* gA1 = (const char*)(g_h1 + (size_t)(tok0 + lr) * HMID + (size_t)ks * RK) + cc * 16;
    const uint32_t sA = (uint32_t)lr * ROWB + cc * 16;
    const int br = tid >> 2;
    const int bc = tid & 3;
    const char* gB0 = (const char*)(g_u0 + (size_t)br * HMID + (size_t)ks * RK) + bc * 16;
    const char* gB1 = (const char*)(g_u1 + (size_t)br * HMID + (size_t)ks * RK) + bc * 16;
    const uint32_t sB = (uint32_t)br * ROWB + bc * 16;

    float acc[2][4][4];
#pragma unroll
    for (int i = 0; i < 2; i++)
#pragma unroll
        for (int j = 0; j < 4; j++)
#pragma unroll
            for (int k = 0; k < 4; k++) acc[i][j][k] = 0.f;

    auto load_stage = [&](int s, int kt) {
        const uint32_t sb = sbase + s * R_STAGE;
        const int go = kt * 64;
        CP_ASYNC16(sb + sA,      gA0 + go);
        CP_ASYNC16(sb + sA + 16, gA0 + go + 16);
        CP_ASYNC16(sb + R_ATILE + sA,      gA1 + go);
        CP_ASYNC16(sb + R_ATILE + sA + 16, gA1 + go + 16);
        CP_ASYNC16(sb + 2 * R_ATILE + sB,           gB0 + go);
        CP_ASYNC16(sb + 2 * R_ATILE + R_BTILE + sB, gB1 + go);
        CP_COMMIT();
    };

    const uint32_t aRow = (uint32_t)(wm + (lid & 15)) * ROWB + (lid >> 4) * 16;
    const uint32_t bRow = (uint32_t)(wn + (lid & 7) + ((lid >> 4) & 1) * 8) * ROWB
                        + ((lid >> 3) & 1) * 16;

    load_stage(0, 0);
    load_stage(1, 1);

    for (int kt = 0; kt < R_KT; kt++) {
        if (kt < R_KT - 1) {
            asm volatile("cp.async.wait_group 1;" ::: "memory");
        } else {
            asm volatile("cp.async.wait_group 0;" ::: "memory");
        }
        __syncthreads();
        if (kt + 2 < R_KT) load_stage((kt + 2) % R_NSTAGE, kt + 2);

        const uint32_t sb = sbase + (kt % R_NSTAGE) * R_STAGE;
#pragma unroll
        for (int k16 = 0; k16 < 2; k16++) {
            const uint32_t kOff = k16 * 32;
            uint32_t b0[2][4], b1f[2][4];
#pragma unroll
            for (int nt2 = 0; nt2 < 2; nt2++) {
                ldsm_x4(b0[nt2],  sb + 2 * R_ATILE + bRow + kOff + nt2 * 16 * ROWB);
                ldsm_x4(b1f[nt2], sb + 2 * R_ATILE + R_BTILE + bRow + kOff + nt2 * 16 * ROWB);
            }
            uint32_t a0[2][4], a1[2][4];
#pragma unroll
            for (int mt = 0; mt < 2; mt++)
                ldsm_x4(a0[mt], sb + aRow + kOff + mt * 16 * ROWB);
#pragma unroll
            for (int mt = 0; mt < 2; mt++)
                ldsm_x4(a1[mt], sb + R_ATILE + aRow + kOff + mt * 16 * ROWB);

#pragma unroll
            for (int mt = 0; mt < 2; mt++)
#pragma unroll
                for (int nt = 0; nt < 4; nt++) {
                    const int n2 = nt >> 1, h = (nt & 1) * 2;
                    mma16816(acc[mt][nt], a0[mt], b0[n2][h], b0[n2][h + 1]);
                }
#pragma unroll
            for (int mt = 0; mt < 2; mt++)
#pragma unroll
                for (int nt = 0; nt < 4; nt++) {
                    const int n2 = nt >> 1, h = (nt & 1) * 2;
                    mma16816(acc[mt][nt], a0[mt], b1f[n2][h], b1f[n2][h + 1]);
                }
#pragma unroll
            for (int mt = 0; mt < 2; mt++)
#pragma unroll
                for (int nt = 0; nt < 4; nt++) {
                    const int n2 = nt >> 1, h = (nt & 1) * 2;
                    mma16816(acc[mt][nt], a1[mt], b0[n2][h], b0[n2][h + 1]);
                }
        }
    }

    // store raw partials (float2, 8B-aligned)
    const int g = lid >> 2;
    const int i2 = (lid & 3) * 2;
#pragma unroll
    for (int nt = 0; nt < 4; nt++) {
        const int col = wn + nt * 8 + i2;
#pragma unroll
        for (int mt = 0; mt < 2; mt++) {
            const int row = wm + mt * 16 + g;
            *reinterpret_cast<float2*>(&g_part[ks][tok0 + row][col]) =
                make_float2(acc[mt][nt][0], acc[mt][nt][1]);
            *reinterpret_cast<float2*>(&g_part[ks][tok0 + row + 8][col]) =
                make_float2(acc[mt][nt][2], acc[mt][nt][3]);
        }
    }
}

// ---------------------------------------------------------------------------
// router_finalize: sum KSPLIT partials + b2, softmax, split, top-2, outputs.
// ---------------------------------------------------------------------------
#define LGS 68
#define SMEM_RFIN (128 * LGS * 4 + 512)

__global__ void __launch_bounds__(256)
router_finalize_kernel(const float* __restrict__ b2, float* __restrict__ out) {
    extern __shared__ float rs[];
    float* lg   = rs;
    float* sinv = rs + 128 * LGS;

    const int tid = threadIdx.x;
    const int tok0 = blockIdx.x * 128;

#pragma unroll
    for (int hh = 0; hh < 8; hh++) {
        int f = tid + 256 * hh;
        int row = f >> 4;
        int c4 = (f & 15) * 4;
        float4 s = *reinterpret_cast<const float4*>(&g_part[0][tok0 + row][c4]);
#pragma unroll
        for (int ks = 1; ks < KSPLIT; ks++) {
            float4 p = *reinterpret_cast<const float4*>(&g_part[ks][tok0 + row][c4]);
            s.x += p.x; s.y += p.y; s.z += p.z; s.w += p.w;
        }
        float4 bb = *reinterpret_cast<const float4*>(&b2[c4]);
        s.x += bb.x; s.y += bb.y; s.z += bb.z; s.w += bb.w;
        *reinterpret_cast<float4*>(&lg[row * LGS + c4]) = s;
    }
    __syncthreads();

    if (tid < 128) {
        const int tok = tok0 + tid;
        float* row = &lg[tid * LGS];
        float mx = -1e30f;
#pragma unroll
        for (int e = 0; e < NEXP; e++) mx = fmaxf(mx, row[e]);
        float s = 0.f;
#pragma unroll
        for (int e = 0; e < NEXP; e++) {
            float ev = expf(row[e] - mx);
            row[e] = ev;
            s += ev;
        }
        float inv = 1.0f / s;
        sinv[tid] = inv;

        float v1 = -1.0f, v2 = -1.0f;
        int i1 = 0, i2v = 0;
#pragma unroll
        for (int e = NSHARED; e < NEXP; e++) {
            float v = row[e];
            if (v > v1)      { v2 = v1; i2v = i1; v1 = v; i1 = e; }
            else if (v > v2) { v2 = v;  i2v = e; }
        }
#pragma unroll
        for (int e = 0; e < NSHARED; e++)
            out[G_OFF + (size_t)tok * NSHARED + e] = row[e] * inv;
        out[LW_OFF + (size_t)tok * TOPK + 0] = v1 * inv;
        out[LW_OFF + (size_t)tok * TOPK + 1] = v2 * inv;
        out[LI_OFF + (size_t)tok * TOPK + 0] = (float)(i1 - NSHARED);
        out[LI_OFF + (size_t)tok * TOPK + 1] = (float)(i2v - NSHARED);
    }
    __syncthreads();

#pragma unroll
    for (int hh = 0; hh < 16; hh++) {
        int f = tid + 256 * hh;
        int tr = f >> 5;
        int ec = (f & 31) * 2;
        float inv = sinv[tr];
        float2 v = *reinterpret_cast<const float2*>(&lg[tr * LGS + ec]);
        v.x *= inv; v.y *= inv;
        *reinterpret_cast<float2*>(
            &out[W_OFF + (size_t)(tok0 + tr) * NEXP + ec]) = v;
    }
}

// ---------------------------------------------------------------------------
extern "C" void kernel_launch(void* const* d_in, const int* in_sizes, int n_in,
                              void* d_out, int out_size) {
    const float* x  = (const float*)d_in[0];
    const float* W1 = (const float*)d_in[1];
    const float* b1 = (const float*)d_in[2];
    const float* W2 = (const float*)d_in[3];
    const float* b2 = (const float*)d_in[4];
    float* out = (float*)d_out;

    static int attr_done = 0;
    if (!attr_done) {
        cudaFuncSetAttribute(gemm1_hmma_kernel,
                             cudaFuncAttributeMaxDynamicSharedMemorySize, SMEM_GEMM);
        cudaFuncSetAttribute(router_partial_kernel,
                             cudaFuncAttributeMaxDynamicSharedMemorySize, SMEM_RPART);
        cudaFuncSetAttribute(router_finalize_kernel,
                             cudaFuncAttributeMaxDynamicSharedMemorySize, SMEM_RFIN);
        attr_done = 1;
    }

    conv_x_kernel<<<(NTOK * DIN) / (256 * 4), 256>>>(x);
    conv_w1_kernel<<<dim3(HMID / 32, DIN / 32), dim3(32, 8)>>>(W1);
    conv_w2_kernel<<<dim3(NEXP / 32, HMID / 32), dim3(32, 8)>>>(W2);
    gemm1_hmma_kernel<<<dim3(HMID / 64, NTOK / 128), 256, SMEM_GEMM>>>(b1);
    router_partial_kernel<<<dim3(NTOK / 128, KSPLIT), 256, SMEM_RPART>>>();
    router_finalize_kernel<<<NTOK / 128, 256, SMEM_RFIN>>>(b2, out);
}

// round 14
// speedup vs baseline: 1.2563x; 1.0573x over previous
#include <cuda_runtime.h>
#include <cuda_fp16.h>
#include <math.h>
#include <stdint.h>

// ---------------------------------------------------------------------------
// Problem constants
// ---------------------------------------------------------------------------
#define NTOK  16384
#define DIN   2048
#define HMID  4096
#define NEXP  64
#define NSHARED 8
#define TOPK  2

// Output layout (flattened concat of the reference tuple)
#define G_OFF  0
#define LW_OFF (NTOK * NSHARED)
#define LI_OFF (LW_OFF + NTOK * TOPK)
#define W_OFF  (LI_OFF + NTOK * TOPK)

// ---------------------------------------------------------------------------
// Scratch (static device arrays; no allocation)
// ---------------------------------------------------------------------------
__device__ __half g_x0[(size_t)NTOK * DIN];           // x limb planes
__device__ __half g_x1[(size_t)NTOK * DIN];
__device__ __half g_w0[(size_t)HMID * DIN];           // W1^T limb planes
__device__ __half g_w1[(size_t)HMID * DIN];
__device__ __half g_h0[(size_t)NTOK * HMID];          // h limb planes
__device__ __half g_h1[(size_t)NTOK * HMID];
__device__ __half g_u0[(size_t)NEXP * HMID];          // W2^T limb planes
__device__ __half g_u1[(size_t)NEXP * HMID];

#define KSPLIT 2
#define RK (HMID / KSPLIT)                            // 2048
__device__ float g_part[KSPLIT][NTOK][NEXP];          // 8.4 MB partial logits

__device__ __forceinline__ uint32_t smem_u32(const void* p) {
    uint32_t a;
    asm("{ .reg .u64 t; cvta.to.shared.u64 t, %1; cvt.u32.u64 %0, t; }"
        : "=r"(a) : "l"(p));
    return a;
}

__device__ __forceinline__ float gelu_exact(float v) {
    return 0.5f * v * (1.0f + erff(v * 0.70710678118654752440f));
}

__device__ __forceinline__ void ldsm_x4(uint32_t* r, uint32_t addr) {
    asm volatile("ldmatrix.sync.aligned.m8n8.x4.shared.b16 {%0,%1,%2,%3}, [%4];"
                 : "=r"(r[0]), "=r"(r[1]), "=r"(r[2]), "=r"(r[3]) : "r"(addr));
}

__device__ __forceinline__ void mma16816(float* d, const uint32_t* a,
                                         uint32_t b0, uint32_t b1) {
    asm volatile(
        "mma.sync.aligned.m16n8k16.row.col.f32.f16.f16.f32 "
        "{%0,%1,%2,%3}, {%4,%5,%6,%7}, {%8,%9}, {%0,%1,%2,%3};"
        : "+f"(d[0]), "+f"(d[1]), "+f"(d[2]), "+f"(d[3])
        : "r"(a[0]), "r"(a[1]), "r"(a[2]), "r"(a[3]), "r"(b0), "r"(b1));
}

#define CP_ASYNC16(dst, src) \
    asm volatile("cp.async.cg.shared.global [%0], [%1], 16;" \
                 :: "r"(dst), "l"(src) : "memory")
#define CP_COMMIT() asm volatile("cp.async.commit_group;" ::: "memory")
#define BAR_SYNC(id, cnt) \
    asm volatile("bar.sync %0, %1;" :: "r"(id), "r"(cnt) : "memory")
#define BAR_ARRIVE(id, cnt) \
    asm volatile("bar.arrive %0, %1;" :: "r"(id), "r"(cnt) : "memory")

__device__ __forceinline__ uint32_t pack_limbs(float x, float y,
                                               float& rx, float& ry) {
    __half hx = __float2half_rn(x), hy = __float2half_rn(y);
    rx = x - __half2float(hx);
    ry = y - __half2float(hy);
    return (uint32_t)__half_as_ushort(hx) | ((uint32_t)__half_as_ushort(hy) << 16);
}

// ---------------------------------------------------------------------------
// conv_x: split x into 2 fp16 limb planes (row-major, K contiguous)
// ---------------------------------------------------------------------------
__global__ void __launch_bounds__(256)
conv_x_kernel(const float* __restrict__ x) {
    size_t i = ((size_t)blockIdx.x * 256 + threadIdx.x) * 4;
    float4 v = *reinterpret_cast<const float4*>(&x[i]);
    float a[4] = {v.x, v.y, v.z, v.w};
    unsigned short u0[4], u1[4];
#pragma unroll
    for (int j = 0; j < 4; j++) {
        __half h0 = __float2half_rn(a[j]);
        float r = a[j] - __half2float(h0);
        u0[j] = __half_as_ushort(h0);
        u1[j] = __half_as_ushort(__float2half_rn(r));
    }
    *reinterpret_cast<uint2*>(&g_x0[i]) =
        make_uint2((uint32_t)u0[0] | ((uint32_t)u0[1] << 16),
                   (uint32_t)u0[2] | ((uint32_t)u0[3] << 16));
    *reinterpret_cast<uint2*>(&g_x1[i]) =
        make_uint2((uint32_t)u1[0] | ((uint32_t)u1[1] << 16),
                   (uint32_t)u1[2] | ((uint32_t)u1[3] << 16));
}

// ---------------------------------------------------------------------------
// conv_w1: transpose W1 [K,N] -> [N,K], split into 2 fp16 limb planes
// ---------------------------------------------------------------------------
__global__ void __launch_bounds__(256)
conv_w1_kernel(const float* __restrict__ W1) {
    __shared__ float tile[32][33];
    const int tx = threadIdx.x, ty = threadIdx.y;
    const int n0 = blockIdx.x * 32;
    const int k0 = blockIdx.y * 32;
#pragma unroll
    for (int j = 0; j < 4; j++)
        tile[ty + j * 8][tx] = W1[(size_t)(k0 + ty + j * 8) * HMID + n0 + tx];
    __syncthreads();
#pragma unroll
    for (int j = 0; j < 4; j++) {
        float v = tile[tx][ty + j * 8];
        __half h0 = __float2half_rn(v);
        float r = v - __half2float(h0);
        size_t o = (size_t)(n0 + ty + j * 8) * DIN + k0 + tx;
        g_w0[o] = h0;
        g_w1[o] = __float2half_rn(r);
    }
}

// ---------------------------------------------------------------------------
// conv_w2: transpose W2 [K=4096, 64] -> [64][4096], split into 2 limb planes
// ---------------------------------------------------------------------------
__global__ void __launch_bounds__(256)
conv_w2_kernel(const float* __restrict__ W2) {
    __shared__ float tile[32][33];
    const int tx = threadIdx.x, ty = threadIdx.y;
    const int n0 = blockIdx.x * 32;
    const int k0 = blockIdx.y * 32;
#pragma unroll
    for (int j = 0; j < 4; j++)
        tile[ty + j * 8][tx] = W2[(size_t)(k0 + ty + j * 8) * NEXP + n0 + tx];
    __syncthreads();
#pragma unroll
    for (int j = 0; j < 4; j++) {
        float v = tile[tx][ty + j * 8];
        __half h0 = __float2half_rn(v);
        float r = v - __half2float(h0);
        size_t o = (size_t)(n0 + ty + j * 8) * HMID + k0 + tx;
        g_u0[o] = h0;
        g_u1[o] = __float2half_rn(r);
    }
}

// ---------------------------------------------------------------------------
// gemm1: h = gelu(x @ W1 + b1) via mma.sync fp16 2-limb, 3 products.
// R11 configuration (measured best): CTA 128x128, K-chunk 32, SW64 swizzle,
// 3 stages, split named-barrier pipeline, 2 CTAs/SM.
// Legacy-HMMA saturation note: tensor-busy is invariant at ~1.36 ms across
// all tried configs => pipe saturated at true rt ~12.6 cyc/SMSP; this is the
// floor for compute_103 (no tcgen05 at this target).
// ---------------------------------------------------------------------------
#define TILE64  (128 * 64)             // 8192 bytes per limb tile
#define STAGE64 (4 * TILE64)           // 32768
#define GSTAGES 3
#define SMEM_GEMM (GSTAGES * STAGE64)  // 98304
#define KT (DIN / 32)                  // 64

__global__ void __launch_bounds__(256, 2)
gemm1_hmma_kernel(const float* __restrict__ b1) {
    extern __shared__ char smem[];
    const uint32_t sbase = smem_u32(smem);
    const int tid = threadIdx.x;
    const int wid = tid >> 5;
    const int lid = tid & 31;
    const int row0 = blockIdx.y * 128;
    const int col0 = blockIdx.x * 128;
    const int wm = (wid >> 2) * 64;
    const int wn = (wid & 3) * 32;

    const int lr = tid >> 1;
    const int cc = (tid & 1) * 2;
    const int mS = (lr >> 1) & 3;
    const uint32_t dst0 = (uint32_t)lr * 64 + (uint32_t)(((cc)     ^ mS) << 4);
    const uint32_t dst1 = (uint32_t)lr * 64 + (uint32_t)(((cc + 1) ^ mS) << 4);
    const char* gA0 = (const char*)(g_x0 + (size_t)(row0 + lr) * DIN) + cc * 16;
    const char* gA1 = (const char*)(g_x1 + (size_t)(row0 + lr) * DIN) + cc * 16;
    const char* gB0 = (const char*)(g_w0 + (size_t)(col0 + lr) * DIN) + cc * 16;
    const char* gB1 = (const char*)(g_w1 + (size_t)(col0 + lr) * DIN) + cc * 16;

    float acc[4][4][4];
#pragma unroll
    for (int i = 0; i < 4; i++)
#pragma unroll
        for (int j = 0; j < 4; j++)
#pragma unroll
            for (int k = 0; k < 4; k++) acc[i][j][k] = 0.f;

    auto load_stage = [&](int s, int kt) {
        const uint32_t sb = sbase + s * STAGE64;
        const int go = kt * 64;
        CP_ASYNC16(sb + dst0,              gA0 + go);
        CP_ASYNC16(sb + dst1,              gA0 + go + 16);
        CP_ASYNC16(sb + TILE64 + dst0,     gA1 + go);
        CP_ASYNC16(sb + TILE64 + dst1,     gA1 + go + 16);
        CP_ASYNC16(sb + 2 * TILE64 + dst0, gB0 + go);
        CP_ASYNC16(sb + 2 * TILE64 + dst1, gB0 + go + 16);
        CP_ASYNC16(sb + 3 * TILE64 + dst0, gB1 + go);
        CP_ASYNC16(sb + 3 * TILE64 + dst1, gB1 + go + 16);
        CP_COMMIT();
    };

    const uint32_t aRowB = (uint32_t)(wm + (lid & 15)) * 64;
    const int cidxA = lid >> 4;
    const int mA = ((lid & 15) >> 1) & 3;
    const int brow = (lid & 7) + ((lid >> 4) & 1) * 8;
    const uint32_t bRowB = (uint32_t)(wn + brow) * 64;
    const int cidxB = (lid >> 3) & 1;
    const int mB = (brow >> 1) & 3;
    uint32_t aCol[2], bCol[2];
#pragma unroll
    for (int k16 = 0; k16 < 2; k16++) {
        aCol[k16] = (uint32_t)((((k16 << 1) | cidxA) ^ mA) << 4);
        bCol[k16] = (uint32_t)((((k16 << 1) | cidxB) ^ mB) << 4);
    }

    // prologue: stages 0,1 in flight; post ready[0] ONLY
    load_stage(0, 0);
    load_stage(1, 1);
    asm volatile("cp.async.wait_group 1;" ::: "memory");
    BAR_ARRIVE(1 + 0, 512);

    int r0 = 0, r1 = 1, r2 = 2;

    for (int kt = 0; kt < KT; kt++) {
        BAR_SYNC(1 + r0, 512);

        const uint32_t sb = sbase + r0 * STAGE64;

        // ================= k16 = 0 =================
        {
            uint32_t b0[2][4], b1f[2][4];
#pragma unroll
            for (int nt2 = 0; nt2 < 2; nt2++) {
                const uint32_t bo = bRowB + nt2 * 1024 + bCol[0];
                ldsm_x4(b0[nt2],  sb + 2 * TILE64 + bo);
                ldsm_x4(b1f[nt2], sb + 3 * TILE64 + bo);
            }
            uint32_t a0[4][4], a1[4][4];
#pragma unroll
            for (int mt = 0; mt < 4; mt++)
                ldsm_x4(a0[mt], sb + aRowB + mt * 1024 + aCol[0]);
#pragma unroll
            for (int mt = 0; mt < 4; mt++)
                ldsm_x4(a1[mt], sb + TILE64 + aRowB + mt * 1024 + aCol[0]);

#pragma unroll
            for (int mt = 0; mt < 4; mt++)
#pragma unroll
                for (int nt = 0; nt < 4; nt++) {
                    const int n2 = nt >> 1, h = (nt & 1) * 2;
                    mma16816(acc[mt][nt], a0[mt], b0[n2][h], b0[n2][h + 1]);
                }
#pragma unroll
            for (int mt = 0; mt < 4; mt++)
#pragma unroll
                for (int nt = 0; nt < 4; nt++) {
                    const int n2 = nt >> 1, h = (nt & 1) * 2;
                    mma16816(acc[mt][nt], a0[mt], b1f[n2][h], b1f[n2][h + 1]);
                }
#pragma unroll
            for (int mt = 0; mt < 4; mt++)
#pragma unroll
                for (int nt = 0; nt < 4; nt++) {
                    const int n2 = nt >> 1, h = (nt & 1) * 2;
                    mma16816(acc[mt][nt], a1[mt], b0[n2][h], b0[n2][h + 1]);
                }
        }

        // ================= k16 = 1 =================
        {
            uint32_t b0[2][4], b1f[2][4];
#pragma unroll
            for (int nt2 = 0; nt2 < 2; nt2++) {
                const uint32_t bo = bRowB + nt2 * 1024 + bCol[1];
                ldsm_x4(b0[nt2],  sb + 2 * TILE64 + bo);
                ldsm_x4(b1f[nt2], sb + 3 * TILE64 + bo);
            }
            uint32_t a0[4][4], a1[4][4];
#pragma unroll
            for (int mt = 0; mt < 4; mt++)
                ldsm_x4(a0[mt], sb + aRowB + mt * 1024 + aCol[1]);
#pragma unroll
            for (int mt = 0; mt < 4; mt++)
                ldsm_x4(a1[mt], sb + TILE64 + aRowB + mt * 1024 + aCol[1]);

            if (kt + 3 < KT) BAR_ARRIVE(4 + r0, 512);
            if (kt >= 1 && kt + 2 < KT) BAR_SYNC(4 + r2, 512);
            if (kt + 2 < KT) load_stage(r2, kt + 2);

#pragma unroll
            for (int mt = 0; mt < 4; mt++)
#pragma unroll
                for (int nt = 0; nt < 4; nt++) {
                    const int n2 = nt >> 1, h = (nt & 1) * 2;
                    mma16816(acc[mt][nt], a0[mt], b0[n2][h], b0[n2][h + 1]);
                }

            if (kt + 1 < KT) {
                if (kt + 2 < KT) {
                    asm volatile("cp.async.wait_group 1;" ::: "memory");
                } else {
                    asm volatile("cp.async.wait_group 0;" ::: "memory");
                }
                BAR_ARRIVE(1 + r1, 512);
            }

#pragma unroll
            for (int mt = 0; mt < 4; mt++)
#pragma unroll
                for (int nt = 0; nt < 4; nt++) {
                    const int n2 = nt >> 1, h = (nt & 1) * 2;
                    mma16816(acc[mt][nt], a0[mt], b1f[n2][h], b1f[n2][h + 1]);
                }
#pragma unroll
            for (int mt = 0; mt < 4; mt++)
#pragma unroll
                for (int nt = 0; nt < 4; nt++) {
                    const int n2 = nt >> 1, h = (nt & 1) * 2;
                    mma16816(acc[mt][nt], a1[mt], b0[n2][h], b0[n2][h + 1]);
                }
        }

        const int t = r0; r0 = r1; r1 = r2; r2 = t;
    }

    // epilogue: bias + gelu + split into fp16 limbs + store
    const int g = lid >> 2;
    const int i2 = (lid & 3) * 2;
#pragma unroll
    for (int nt = 0; nt < 4; nt++) {
        const int col = col0 + wn + nt * 8 + i2;
        const float bx = b1[col], by = b1[col + 1];
#pragma unroll
        for (int mt = 0; mt < 4; mt++) {
            const int row = row0 + wm + mt * 16 + g;
            float lox = gelu_exact(acc[mt][nt][0] + bx);
            float loy = gelu_exact(acc[mt][nt][1] + by);
            float hix = gelu_exact(acc[mt][nt][2] + bx);
            float hiy = gelu_exact(acc[mt][nt][3] + by);
            float r0f, r1f, r2f, r3f;
            uint32_t p0 = pack_limbs(lox, loy, r0f, r1f);
            uint32_t p1 = pack_limbs(hix, hiy, r2f, r3f);
            size_t o0 = (size_t)row * HMID + col;
            size_t o1 = (size_t)(row + 8) * HMID + col;
            *reinterpret_cast<uint32_t*>(&g_h0[o0]) = p0;
            *reinterpret_cast<uint32_t*>(&g_h0[o1]) = p1;
            __half q0 = __float2half_rn(r0f), q1 = __float2half_rn(r1f);
            __half q2 = __float2half_rn(r2f), q3 = __float2half_rn(r3f);
            *reinterpret_cast<uint32_t*>(&g_h1[o0]) =
                (uint32_t)__half_as_ushort(q0) | ((uint32_t)__half_as_ushort(q1) << 16);
            *reinterpret_cast<uint32_t*>(&g_h1[o1]) =
                (uint32_t)__half_as_ushort(q2) | ((uint32_t)__half_as_ushort(q3) << 16);
        }
    }
}

// ---------------------------------------------------------------------------
// router_partial: partial logits over a K-slice of 2048 (KSPLIT=2).
// grid (NTOK/128, KSPLIT), 2 CTAs/SM. Stores raw fp32 partials (no bias).
// ---------------------------------------------------------------------------
#define ROWB 80
#define R_ATILE (128 * ROWB)
#define R_BTILE (64 * ROWB)
#define R_STAGE (2 * R_ATILE + 2 * R_BTILE)  // 30720
#define R_NSTAGE 3
#define R_KT (RK / 32)                       // 64
#define SMEM_RPART (R_NSTAGE * R_STAGE)      // 92160

__global__ void __launch_bounds__(256, 2)
router_partial_kernel() {
    extern __shared__ char smem[];
    const uint32_t sbase = smem_u32(smem);

    const int tid = threadIdx.x;
    const int wid = tid >> 5;
    const int lid = tid & 31;
    const int tok0 = blockIdx.x * 128;
    const int ks = blockIdx.y;
    const int wm = (wid >> 1) * 32;
    const int wn = (wid & 1) * 32;

    const int lr  = tid >> 1;
    const int cc  = (tid & 1) * 2;
    const char* gA0 = (const char*)(g_h0 + (size_t)(tok0 + lr) * HMID + (size_t)ks * RK) + cc * 16;
    const char* gA1 = (const char*)(g_h1 + (size_t)(tok0 + lr) * HMID + (size_t)ks * RK) + cc * 16;
    const uint32_t sA = (uint32_t)lr * ROWB + cc * 16;
    const int br = tid >> 2;
    const int bc = tid & 3;
    const char* gB0 = (const char*)(g_u0 + (size_t)br * HMID + (size_t)ks * RK) + bc * 16;
    const char* gB1 = (const char*)(g_u1 + (size_t)br * HMID + (size_t)ks * RK) + bc * 16;
    const uint32_t sB = (uint32_t)br * ROWB + bc * 16;

    float acc[2][4][4];
#pragma unroll
    for (int i = 0; i < 2; i++)
#pragma unroll
        for (int j = 0; j < 4; j++)
#pragma unroll
            for (int k = 0; k < 4; k++) acc[i][j][k] = 0.f;

    auto load_stage = [&](int s, int kt) {
        const uint32_t sb = sbase + s * R_STAGE;
        const int go = kt * 64;
        CP_ASYNC16(sb + sA,      gA0 + go);
        CP_ASYNC16(sb + sA + 16, gA0 + go + 16);
        CP_ASYNC16(sb + R_ATILE + sA,      gA1 + go);
        CP_ASYNC16(sb + R_ATILE + sA + 16, gA1 + go + 16);
        CP_ASYNC16(sb + 2 * R_ATILE + sB,           gB0 + go);
        CP_ASYNC16(sb + 2 * R_ATILE + R_BTILE + sB, gB1 + go);
        CP_COMMIT();
    };

    const uint32_t aRow = (uint32_t)(wm + (lid & 15)) * ROWB + (lid >> 4) * 16;
    const uint32_t bRow = (uint32_t)(wn + (lid & 7) + ((lid >> 4) & 1) * 8) * ROWB
                        + ((lid >> 3) & 1) * 16;

    load_stage(0, 0);
    load_stage(1, 1);

    for (int kt = 0; kt < R_KT; kt++) {
        if (kt < R_KT - 1) {
            asm volatile("cp.async.wait_group 1;" ::: "memory");
        } else {
            asm volatile("cp.async.wait_group 0;" ::: "memory");
        }
        __syncthreads();
        if (kt + 2 < R_KT) load_stage((kt + 2) % R_NSTAGE, kt + 2);

        const uint32_t sb = sbase + (kt % R_NSTAGE) * R_STAGE;
#pragma unroll
        for (int k16 = 0; k16 < 2; k16++) {
            const uint32_t kOff = k16 * 32;
            uint32_t b0[2][4], b1f[2][4];
#pragma unroll
            for (int nt2 = 0; nt2 < 2; nt2++) {
                ldsm_x4(b0[nt2],  sb + 2 * R_ATILE + bRow + kOff + nt2 * 16 * ROWB);
                ldsm_x4(b1f[nt2], sb + 2 * R_ATILE + R_BTILE + bRow + kOff + nt2 * 16 * ROWB);
            }
            uint32_t a0[2][4], a1[2][4];
#pragma unroll
            for (int mt = 0; mt < 2; mt++)
                ldsm_x4(a0[mt], sb + aRow + kOff + mt * 16 * ROWB);
#pragma unroll
            for (int mt = 0; mt < 2; mt++)
                ldsm_x4(a1[mt], sb + R_ATILE + aRow + kOff + mt * 16 * ROWB);

#pragma unroll
            for (int mt = 0; mt < 2; mt++)
#pragma unroll
                for (int nt = 0; nt < 4; nt++) {
                    const int n2 = nt >> 1, h = (nt & 1) * 2;
                    mma16816(acc[mt][nt], a0[mt], b0[n2][h], b0[n2][h + 1]);
                }
#pragma unroll
            for (int mt = 0; mt < 2; mt++)
#pragma unroll
                for (int nt = 0; nt < 4; nt++) {
                    const int n2 = nt >> 1, h = (nt & 1) * 2;
                    mma16816(acc[mt][nt], a0[mt], b1f[n2][h], b1f[n2][h + 1]);
                }
#pragma unroll
            for (int mt = 0; mt < 2; mt++)
#pragma unroll
                for (int nt = 0; nt < 4; nt++) {
                    const int n2 = nt >> 1, h = (nt & 1) * 2;
                    mma16816(acc[mt][nt], a1[mt], b0[n2][h], b0[n2][h + 1]);
                }
        }
    }

    // store raw partials (float2, 8B-aligned)
    const int g = lid >> 2;
    const int i2 = (lid & 3) * 2;
#pragma unroll
    for (int nt = 0; nt < 4; nt++) {
        const int col = wn + nt * 8 + i2;
#pragma unroll
        for (int mt = 0; mt < 2; mt++) {
            const int row = wm + mt * 16 + g;
            *reinterpret_cast<float2*>(&g_part[ks][tok0 + row][col]) =
                make_float2(acc[mt][nt][0], acc[mt][nt][1]);
            *reinterpret_cast<float2*>(&g_part[ks][tok0 + row + 8][col]) =
                make_float2(acc[mt][nt][2], acc[mt][nt][3]);
        }
    }
}

// ---------------------------------------------------------------------------
// router_finalize: sum KSPLIT partials + b2, softmax, split, top-2, outputs.
// ---------------------------------------------------------------------------
#define LGS 68
#define SMEM_RFIN (128 * LGS * 4 + 512)

__global__ void __launch_bounds__(256)
router_finalize_kernel(const float* __restrict__ b2, float* __restrict__ out) {
    extern __shared__ float rs[];
    float* lg   = rs;
    float* sinv = rs + 128 * LGS;

    const int tid = threadIdx.x;
    const int tok0 = blockIdx.x * 128;

#pragma unroll
    for (int hh = 0; hh < 8; hh++) {
        int f = tid + 256 * hh;
        int row = f >> 4;
        int c4 = (f & 15) * 4;
        float4 s = *reinterpret_cast<const float4*>(&g_part[0][tok0 + row][c4]);
#pragma unroll
        for (int ks = 1; ks < KSPLIT; ks++) {
            float4 p = *reinterpret_cast<const float4*>(&g_part[ks][tok0 + row][c4]);
            s.x += p.x; s.y += p.y; s.z += p.z; s.w += p.w;
        }
        float4 bb = *reinterpret_cast<const float4*>(&b2[c4]);
        s.x += bb.x; s.y += bb.y; s.z += bb.z; s.w += bb.w;
        *reinterpret_cast<float4*>(&lg[row * LGS + c4]) = s;
    }
    __syncthreads();

    if (tid < 128) {
        const int tok = tok0 + tid;
        float* row = &lg[tid * LGS];
        float mx = -1e30f;
#pragma unroll
        for (int e = 0; e < NEXP; e++) mx = fmaxf(mx, row[e]);
        float s = 0.f;
#pragma unroll
        for (int e = 0; e < NEXP; e++) {
            float ev = expf(row[e] - mx);
            row[e] = ev;
            s += ev;
        }
        float inv = 1.0f / s;
        sinv[tid] = inv;

        float v1 = -1.0f, v2 = -1.0f;
        int i1 = 0, i2v = 0;
#pragma unroll
        for (int e = NSHARED; e < NEXP; e++) {
            float v = row[e];
            if (v > v1)      { v2 = v1; i2v = i1; v1 = v; i1 = e; }
            else if (v > v2) { v2 = v;  i2v = e; }
        }
#pragma unroll
        for (int e = 0; e < NSHARED; e++)
            out[G_OFF + (size_t)tok * NSHARED + e] = row[e] * inv;
        out[LW_OFF + (size_t)tok * TOPK + 0] = v1 * inv;
        out[LW_OFF + (size_t)tok * TOPK + 1] = v2 * inv;
        out[LI_OFF + (size_t)tok * TOPK + 0] = (float)(i1 - NSHARED);
        out[LI_OFF + (size_t)tok * TOPK + 1] = (float)(i2v - NSHARED);
    }
    __syncthreads();

#pragma unroll
    for (int hh = 0; hh < 16; hh++) {
        int f = tid + 256 * hh;
        int tr = f >> 5;
        int ec = (f & 31) * 2;
        float inv = sinv[tr];
        float2 v = *reinterpret_cast<const float2*>(&lg[tr * LGS + ec]);
        v.x *= inv; v.y *= inv;
        *reinterpret_cast<float2*>(
            &out[W_OFF + (size_t)(tok0 + tr) * NEXP + ec]) = v;
    }
}

// ---------------------------------------------------------------------------
extern "C" void kernel_launch(void* const* d_in, const int* in_sizes, int n_in,
                              void* d_out, int out_size) {
    const float* x  = (const float*)d_in[0];
    const float* W1 = (const float*)d_in[1];
    const float* b1 = (const float*)d_in[2];
    const float* W2 = (const float*)d_in[3];
    const float* b2 = (const float*)d_in[4];
    float* out = (float*)d_out;

    static int attr_done = 0;
    if (!attr_done) {
        cudaFuncSetAttribute(gemm1_hmma_kernel,
                             cudaFuncAttributeMaxDynamicSharedMemorySize, SMEM_GEMM);
        cudaFuncSetAttribute(router_partial_kernel,
                             cudaFuncAttributeMaxDynamicSharedMemorySize, SMEM_RPART);
        cudaFuncSetAttribute(router_finalize_kernel,
                             cudaFuncAttributeMaxDynamicSharedMemorySize, SMEM_RFIN);
        attr_done = 1;
    }

    conv_x_kernel<<<(NTOK * DIN) / (256 * 4), 256>>>(x);
    conv_w1_kernel<<<dim3(HMID / 32, DIN / 32), dim3(32, 8)>>>(W1);
    conv_w2_kernel<<<dim3(NEXP / 32, HMID / 32), dim3(32, 8)>>>(W2);
    gemm1_hmma_kernel<<<dim3(HMID / 128, NTOK / 128), 256, SMEM_GEMM>>>(b1);
    router_partial_kernel<<<dim3(NTOK / 128, KSPLIT), 256, SMEM_RPART>>>();
    router_finalize_kernel<<<NTOK / 128, 256, SMEM_RFIN>>>(b2, out);
}

// round 15
// speedup vs baseline: 1.2884x; 1.0256x over previous
#include <cuda_runtime.h>
#include <cuda_fp16.h>
#include <math.h>
#include <stdint.h>

// ---------------------------------------------------------------------------
// Problem constants
// ---------------------------------------------------------------------------
#define NTOK  16384
#define DIN   2048
#define HMID  4096
#define NEXP  64
#define NSHARED 8
#define TOPK  2

// Output layout (flattened concat of the reference tuple)
#define G_OFF  0
#define LW_OFF (NTOK * NSHARED)
#define LI_OFF (LW_OFF + NTOK * TOPK)
#define W_OFF  (LI_OFF + NTOK * TOPK)

// ---------------------------------------------------------------------------
// Scratch (static device arrays; no allocation)
// ---------------------------------------------------------------------------
__device__ __half g_x0[(size_t)NTOK * DIN];           // x limb planes
__device__ __half g_x1[(size_t)NTOK * DIN];
__device__ __half g_w0[(size_t)HMID * DIN];           // W1^T limb planes
__device__ __half g_w1[(size_t)HMID * DIN];
__device__ __half g_u0[(size_t)NEXP * HMID];          // W2^T limb planes
__device__ __half g_u1[(size_t)NEXP * HMID];
__device__ float  g_logits[NTOK][NEXP];               // fused router logits

__device__ __forceinline__ uint32_t smem_u32(const void* p) {
    uint32_t a;
    asm("{ .reg .u64 t; cvta.to.shared.u64 t, %1; cvt.u32.u64 %0, t; }"
        : "=r"(a) : "l"(p));
    return a;
}

__device__ __forceinline__ float gelu_exact(float v) {
    return 0.5f * v * (1.0f + erff(v * 0.70710678118654752440f));
}

__device__ __forceinline__ void ldsm_x4(uint32_t* r, uint32_t addr) {
    asm volatile("ldmatrix.sync.aligned.m8n8.x4.shared.b16 {%0,%1,%2,%3}, [%4];"
                 : "=r"(r[0]), "=r"(r[1]), "=r"(r[2]), "=r"(r[3]) : "r"(addr));
}

__device__ __forceinline__ void mma16816(float* d, const uint32_t* a,
                                         uint32_t b0, uint32_t b1) {
    asm volatile(
        "mma.sync.aligned.m16n8k16.row.col.f32.f16.f16.f32 "
        "{%0,%1,%2,%3}, {%4,%5,%6,%7}, {%8,%9}, {%0,%1,%2,%3};"
        : "+f"(d[0]), "+f"(d[1]), "+f"(d[2]), "+f"(d[3])
        : "r"(a[0]), "r"(a[1]), "r"(a[2]), "r"(a[3]), "r"(b0), "r"(b1));
}

#define CP_ASYNC16(dst, src) \
    asm volatile("cp.async.cg.shared.global [%0], [%1], 16;" \
                 :: "r"(dst), "l"(src) : "memory")
#define CP_COMMIT() asm volatile("cp.async.commit_group;" ::: "memory")
#define BAR_SYNC(id, cnt) \
    asm volatile("bar.sync %0, %1;" :: "r"(id), "r"(cnt) : "memory")
#define BAR_ARRIVE(id, cnt) \
    asm volatile("bar.arrive %0, %1;" :: "r"(id), "r"(cnt) : "memory")

__device__ __forceinline__ uint32_t pack_limbs(float x, float y,
                                               float& rx, float& ry) {
    __half hx = __float2half_rn(x), hy = __float2half_rn(y);
    rx = x - __half2float(hx);
    ry = y - __half2float(hy);
    return (uint32_t)__half_as_ushort(hx) | ((uint32_t)__half_as_ushort(hy) << 16);
}

// ---------------------------------------------------------------------------
// conv_x: split x into 2 fp16 limb planes (row-major, K contiguous)
// ---------------------------------------------------------------------------
__global__ void __launch_bounds__(256)
conv_x_kernel(const float* __restrict__ x) {
    size_t i = ((size_t)blockIdx.x * 256 + threadIdx.x) * 4;
    float4 v = *reinterpret_cast<const float4*>(&x[i]);
    float a[4] = {v.x, v.y, v.z, v.w};
    unsigned short u0[4], u1[4];
#pragma unroll
    for (int j = 0; j < 4; j++) {
        __half h0 = __float2half_rn(a[j]);
        float r = a[j] - __half2float(h0);
        u0[j] = __half_as_ushort(h0);
        u1[j] = __half_as_ushort(__float2half_rn(r));
    }
    *reinterpret_cast<uint2*>(&g_x0[i]) =
        make_uint2((uint32_t)u0[0] | ((uint32_t)u0[1] << 16),
                   (uint32_t)u0[2] | ((uint32_t)u0[3] << 16));
    *reinterpret_cast<uint2*>(&g_x1[i]) =
        make_uint2((uint32_t)u1[0] | ((uint32_t)u1[1] << 16),
                   (uint32_t)u1[2] | ((uint32_t)u1[3] << 16));
}

// ---------------------------------------------------------------------------
// conv_w1: transpose W1 [K,N] -> [N,K], split into 2 fp16 limb planes
// ---------------------------------------------------------------------------
__global__ void __launch_bounds__(256)
conv_w1_kernel(const float* __restrict__ W1) {
    __shared__ float tile[32][33];
    const int tx = threadIdx.x, ty = threadIdx.y;
    const int n0 = blockIdx.x * 32;
    const int k0 = blockIdx.y * 32;
#pragma unroll
    for (int j = 0; j < 4; j++)
        tile[ty + j * 8][tx] = W1[(size_t)(k0 + ty + j * 8) * HMID + n0 + tx];
    __syncthreads();
#pragma unroll
    for (int j = 0; j < 4; j++) {
        float v = tile[tx][ty + j * 8];
        __half h0 = __float2half_rn(v);
        float r = v - __half2float(h0);
        size_t o = (size_t)(n0 + ty + j * 8) * DIN + k0 + tx;
        g_w0[o] = h0;
        g_w1[o] = __float2half_rn(r);
    }
}

// ---------------------------------------------------------------------------
// conv_w2: transpose W2 [K=4096, 64] -> [64][4096], split into 2 limb planes
// ---------------------------------------------------------------------------
__global__ void __launch_bounds__(256)
conv_w2_kernel(const float* __restrict__ W2) {
    __shared__ float tile[32][33];
    const int tx = threadIdx.x, ty = threadIdx.y;
    const int n0 = blockIdx.x * 32;
    const int k0 = blockIdx.y * 32;
#pragma unroll
    for (int j = 0; j < 4; j++)
        tile[ty + j * 8][tx] = W2[(size_t)(k0 + ty + j * 8) * NEXP + n0 + tx];
    __syncthreads();
#pragma unroll
    for (int j = 0; j < 4; j++) {
        float v = tile[tx][ty + j * 8];
        __half h0 = __float2half_rn(v);
        float r = v - __half2float(h0);
        size_t o = (size_t)(n0 + ty + j * 8) * HMID + k0 + tx;
        g_u0[o] = h0;
        g_u1[o] = __float2half_rn(r);
    }
}

// ---------------------------------------------------------------------------
// zero_logits: reset the fused logits accumulator each launch
// ---------------------------------------------------------------------------
__global__ void __launch_bounds__(256)
zero_logits_kernel() {
    size_t i = ((size_t)blockIdx.x * 256 + threadIdx.x) * 4;
    *reinterpret_cast<float4*>(&g_logits[0][0] + i) =
        make_float4(0.f, 0.f, 0.f, 0.f);
}

// ---------------------------------------------------------------------------
// gemm1 + fused router partial:
//   mainloop: h = x @ W1 (fp16 2-limb, 3 products) — unchanged R11 config
//   epilogue: bias+gelu -> h limbs staged in smem; load W2^T K-slice;
//             3-product HMMA 128 tok x 64 exp x K=128; atomicAdd to g_logits.
// SMEM reuse in epilogue: H0 [0,32K), H1 [32K,64K), U0 [64K,80K), U1 [80K,96K)
// h smem layout: [token 0..127][kcol 0..127], 256B rows,
//   chunk swizzle c' = (kcol>>3) ^ (token & 15). Same layout for U (exp rows).
// ---------------------------------------------------------------------------
#define TILE64  (128 * 64)
#define STAGE64 (4 * TILE64)
#define GSTAGES 3
#define SMEM_GEMM (GSTAGES * STAGE64)  // 98304
#define KT (DIN / 32)                  // 64
#define H0_OFF 0
#define H1_OFF 32768
#define U0_OFF 65536
#define U1_OFF 81920

__global__ void __launch_bounds__(256, 2)
gemm1_hmma_kernel(const float* __restrict__ b1) {
    extern __shared__ char smem[];
    const uint32_t sbase = smem_u32(smem);
    const int tid = threadIdx.x;
    const int wid = tid >> 5;
    const int lid = tid & 31;
    const int row0 = blockIdx.y * 128;
    const int col0 = blockIdx.x * 128;
    const int wm = (wid >> 2) * 64;
    const int wn = (wid & 3) * 32;

    const int lr = tid >> 1;
    const int cc = (tid & 1) * 2;
    const int mS = (lr >> 1) & 3;
    const uint32_t dst0 = (uint32_t)lr * 64 + (uint32_t)(((cc)     ^ mS) << 4);
    const uint32_t dst1 = (uint32_t)lr * 64 + (uint32_t)(((cc + 1) ^ mS) << 4);
    const char* gA0 = (const char*)(g_x0 + (size_t)(row0 + lr) * DIN) + cc * 16;
    const char* gA1 = (const char*)(g_x1 + (size_t)(row0 + lr) * DIN) + cc * 16;
    const char* gB0 = (const char*)(g_w0 + (size_t)(col0 + lr) * DIN) + cc * 16;
    const char* gB1 = (const char*)(g_w1 + (size_t)(col0 + lr) * DIN) + cc * 16;

    float acc[4][4][4];
#pragma unroll
    for (int i = 0; i < 4; i++)
#pragma unroll
        for (int j = 0; j < 4; j++)
#pragma unroll
            for (int k = 0; k < 4; k++) acc[i][j][k] = 0.f;

    auto load_stage = [&](int s, int kt) {
        const uint32_t sb = sbase + s * STAGE64;
        const int go = kt * 64;
        CP_ASYNC16(sb + dst0,              gA0 + go);
        CP_ASYNC16(sb + dst1,              gA0 + go + 16);
        CP_ASYNC16(sb + TILE64 + dst0,     gA1 + go);
        CP_ASYNC16(sb + TILE64 + dst1,     gA1 + go + 16);
        CP_ASYNC16(sb + 2 * TILE64 + dst0, gB0 + go);
        CP_ASYNC16(sb + 2 * TILE64 + dst1, gB0 + go + 16);
        CP_ASYNC16(sb + 3 * TILE64 + dst0, gB1 + go);
        CP_ASYNC16(sb + 3 * TILE64 + dst1, gB1 + go + 16);
        CP_COMMIT();
    };

    const uint32_t aRowB = (uint32_t)(wm + (lid & 15)) * 64;
    const int cidxA = lid >> 4;
    const int mA = ((lid & 15) >> 1) & 3;
    const int brow = (lid & 7) + ((lid >> 4) & 1) * 8;
    const uint32_t bRowB = (uint32_t)(wn + brow) * 64;
    const int cidxB = (lid >> 3) & 1;
    const int mB = (brow >> 1) & 3;
    uint32_t aCol[2], bCol[2];
#pragma unroll
    for (int k16 = 0; k16 < 2; k16++) {
        aCol[k16] = (uint32_t)((((k16 << 1) | cidxA) ^ mA) << 4);
        bCol[k16] = (uint32_t)((((k16 << 1) | cidxB) ^ mB) << 4);
    }

    // prologue: stages 0,1 in flight; post ready[0] ONLY
    load_stage(0, 0);
    load_stage(1, 1);
    asm volatile("cp.async.wait_group 1;" ::: "memory");
    BAR_ARRIVE(1 + 0, 512);

    int r0 = 0, r1 = 1, r2 = 2;

    for (int kt = 0; kt < KT; kt++) {
        BAR_SYNC(1 + r0, 512);

        const uint32_t sb = sbase + r0 * STAGE64;

        // ================= k16 = 0 =================
        {
            uint32_t b0[2][4], b1f[2][4];
#pragma unroll
            for (int nt2 = 0; nt2 < 2; nt2++) {
                const uint32_t bo = bRowB + nt2 * 1024 + bCol[0];
                ldsm_x4(b0[nt2],  sb + 2 * TILE64 + bo);
                ldsm_x4(b1f[nt2], sb + 3 * TILE64 + bo);
            }
            uint32_t a0[4][4], a1[4][4];
#pragma unroll
            for (int mt = 0; mt < 4; mt++)
                ldsm_x4(a0[mt], sb + aRowB + mt * 1024 + aCol[0]);
#pragma unroll
            for (int mt = 0; mt < 4; mt++)
                ldsm_x4(a1[mt], sb + TILE64 + aRowB + mt * 1024 + aCol[0]);

#pragma unroll
            for (int mt = 0; mt < 4; mt++)
#pragma unroll
                for (int nt = 0; nt < 4; nt++) {
                    const int n2 = nt >> 1, h = (nt & 1) * 2;
                    mma16816(acc[mt][nt], a0[mt], b0[n2][h], b0[n2][h + 1]);
                }
#pragma unroll
            for (int mt = 0; mt < 4; mt++)
#pragma unroll
                for (int nt = 0; nt < 4; nt++) {
                    const int n2 = nt >> 1, h = (nt & 1) * 2;
                    mma16816(acc[mt][nt], a0[mt], b1f[n2][h], b1f[n2][h + 1]);
                }
#pragma unroll
            for (int mt = 0; mt < 4; mt++)
#pragma unroll
                for (int nt = 0; nt < 4; nt++) {
                    const int n2 = nt >> 1, h = (nt & 1) * 2;
                    mma16816(acc[mt][nt], a1[mt], b0[n2][h], b0[n2][h + 1]);
                }
        }

        // ================= k16 = 1 =================
        {
            uint32_t b0[2][4], b1f[2][4];
#pragma unroll
            for (int nt2 = 0; nt2 < 2; nt2++) {
                const uint32_t bo = bRowB + nt2 * 1024 + bCol[1];
                ldsm_x4(b0[nt2],  sb + 2 * TILE64 + bo);
                ldsm_x4(b1f[nt2], sb + 3 * TILE64 + bo);
            }
            uint32_t a0[4][4], a1[4][4];
#pragma unroll
            for (int mt = 0; mt < 4; mt++)
                ldsm_x4(a0[mt], sb + aRowB + mt * 1024 + aCol[1]);
#pragma unroll
            for (int mt = 0; mt < 4; mt++)
                ldsm_x4(a1[mt], sb + TILE64 + aRowB + mt * 1024 + aCol[1]);

            if (kt + 3 < KT) BAR_ARRIVE(4 + r0, 512);
            if (kt >= 1 && kt + 2 < KT) BAR_SYNC(4 + r2, 512);
            if (kt + 2 < KT) load_stage(r2, kt + 2);

#pragma unroll
            for (int mt = 0; mt < 4; mt++)
#pragma unroll
                for (int nt = 0; nt < 4; nt++) {
                    const int n2 = nt >> 1, h = (nt & 1) * 2;
                    mma16816(acc[mt][nt], a0[mt], b0[n2][h], b0[n2][h + 1]);
                }

            if (kt + 1 < KT) {
                if (kt + 2 < KT) {
                    asm volatile("cp.async.wait_group 1;" ::: "memory");
                } else {
                    asm volatile("cp.async.wait_group 0;" ::: "memory");
                }
                BAR_ARRIVE(1 + r1, 512);
            }

#pragma unroll
            for (int mt = 0; mt < 4; mt++)
#pragma unroll
                for (int nt = 0; nt < 4; nt++) {
                    const int n2 = nt >> 1, h = (nt & 1) * 2;
                    mma16816(acc[mt][nt], a0[mt], b1f[n2][h], b1f[n2][h + 1]);
                }
#pragma unroll
            for (int mt = 0; mt < 4; mt++)
#pragma unroll
                for (int nt = 0; nt < 4; nt++) {
                    const int n2 = nt >> 1, h = (nt & 1) * 2;
                    mma16816(acc[mt][nt], a1[mt], b0[n2][h], b0[n2][h + 1]);
                }
        }

        const int t = r0; r0 = r1; r1 = r2; r2 = t;
    }

    // =========================== fused epilogue ===========================
    __syncthreads();   // all pipeline smem reads complete

    // prefetch W2^T limb K-slices: [64 exp][128 k], 256B rows, swizzled
    {
        const int ue = tid >> 2;
        const int c0 = (tid & 3) * 4;
        const char* gu0 = (const char*)(g_u0 + (size_t)ue * HMID + col0);
        const char* gu1 = (const char*)(g_u1 + (size_t)ue * HMID + col0);
#pragma unroll
        for (int c = 0; c < 4; c++) {
            int ch = c0 + c;
            uint32_t d = (uint32_t)ue * 256 + (uint32_t)((ch ^ (ue & 15)) << 4);
            CP_ASYNC16(sbase + U0_OFF + d, gu0 + ch * 16);
            CP_ASYNC16(sbase + U1_OFF + d, gu1 + ch * 16);
        }
        CP_COMMIT();
    }

    // bias + gelu + split h into fp16 limbs staged in smem
    const int g = lid >> 2;
    const int i2 = (lid & 3) * 2;
#pragma unroll
    for (int nt = 0; nt < 4; nt++) {
        const int col = wn + nt * 8 + i2;           // kcol within tile
        const float bx = b1[col0 + col], by = b1[col0 + col + 1];
        const uint32_t chunkOff = (uint32_t)((col & 7) * 2);
        const uint32_t chunkIdx = (uint32_t)(col >> 3);
#pragma unroll
        for (int mt = 0; mt < 4; mt++) {
            const int rowL = wm + mt * 16 + g;
            const int rowH = rowL + 8;
            float lox = gelu_exact(acc[mt][nt][0] + bx);
            float loy = gelu_exact(acc[mt][nt][1] + by);
            float hix = gelu_exact(acc[mt][nt][2] + bx);
            float hiy = gelu_exact(acc[mt][nt][3] + by);
            float r0f, r1f, r2f, r3f;
            uint32_t p0 = pack_limbs(lox, loy, r0f, r1f);
            uint32_t p1 = pack_limbs(hix, hiy, r2f, r3f);
            uint32_t q0 = (uint32_t)__half_as_ushort(__float2half_rn(r0f)) |
                          ((uint32_t)__half_as_ushort(__float2half_rn(r1f)) << 16);
            uint32_t q1 = (uint32_t)__half_as_ushort(__float2half_rn(r2f)) |
                          ((uint32_t)__half_as_ushort(__float2half_rn(r3f)) << 16);
            uint32_t stL = (uint32_t)rowL * 256 +
                           ((chunkIdx ^ (uint32_t)(rowL & 15)) << 4) + chunkOff;
            uint32_t stH = (uint32_t)rowH * 256 +
                           ((chunkIdx ^ (uint32_t)(rowH & 15)) << 4) + chunkOff;
            *reinterpret_cast<uint32_t*>(smem + H0_OFF + stL) = p0;
            *reinterpret_cast<uint32_t*>(smem + H0_OFF + stH) = p1;
            *reinterpret_cast<uint32_t*>(smem + H1_OFF + stL) = q0;
            *reinterpret_cast<uint32_t*>(smem + H1_OFF + stH) = q1;
        }
    }
    asm volatile("cp.async.wait_group 0;" ::: "memory");
    __syncthreads();

    // fused MMA: 128 tokens x 64 experts, K = 128 (this CTA's col slice)
    const int wmF = (wid >> 1) * 32;
    const int wnF = (wid & 1) * 32;
    const int aRowM = lid & 15;
    float accF[2][4][4];
#pragma unroll
    for (int i = 0; i < 2; i++)
#pragma unroll
        for (int j = 0; j < 4; j++)
#pragma unroll
            for (int k = 0; k < 4; k++) accF[i][j][k] = 0.f;

#pragma unroll
    for (int k16 = 0; k16 < 8; k16++) {
        uint32_t b0[2][4], b1f[2][4];
#pragma unroll
        for (int nt2 = 0; nt2 < 2; nt2++) {
            const uint32_t rb = (uint32_t)(wnF + nt2 * 16 + brow) * 256 +
                                (uint32_t)(((k16 * 2 + cidxB) ^ brow) << 4);
            ldsm_x4(b0[nt2],  sbase + U0_OFF + rb);
            ldsm_x4(b1f[nt2], sbase + U1_OFF + rb);
        }
        uint32_t a0[2][4], a1[2][4];
#pragma unroll
        for (int mt = 0; mt < 2; mt++) {
            const uint32_t ra = (uint32_t)(wmF + mt * 16 + aRowM) * 256 +
                                (uint32_t)(((k16 * 2 + cidxA) ^ aRowM) << 4);
            ldsm_x4(a0[mt], sbase + H0_OFF + ra);
            ldsm_x4(a1[mt], sbase + H1_OFF + ra);
        }
#pragma unroll
        for (int mt = 0; mt < 2; mt++)
#pragma unroll
            for (int nt = 0; nt < 4; nt++) {
                const int n2 = nt >> 1, h = (nt & 1) * 2;
                mma16816(accF[mt][nt], a0[mt], b0[n2][h], b0[n2][h + 1]);
            }
#pragma unroll
        for (int mt = 0; mt < 2; mt++)
#pragma unroll
            for (int nt = 0; nt < 4; nt++) {
                const int n2 = nt >> 1, h = (nt & 1) * 2;
                mma16816(accF[mt][nt], a0[mt], b1f[n2][h], b1f[n2][h + 1]);
            }
#pragma unroll
        for (int mt = 0; mt < 2; mt++)
#pragma unroll
            for (int nt = 0; nt < 4; nt++) {
                const int n2 = nt >> 1, h = (nt & 1) * 2;
                mma16816(accF[mt][nt], a1[mt], b0[n2][h], b0[n2][h + 1]);
            }
    }

    // accumulate partial logits
#pragma unroll
    for (int nt = 0; nt < 4; nt++) {
        const int ce = wnF + nt * 8 + i2;
#pragma unroll
        for (int mt = 0; mt < 2; mt++) {
            const int rt = row0 + wmF + mt * 16 + g;
            atomicAdd(&g_logits[rt][ce],         accF[mt][nt][0]);
            atomicAdd(&g_logits[rt][ce + 1],     accF[mt][nt][1]);
            atomicAdd(&g_logits[rt + 8][ce],     accF[mt][nt][2]);
            atomicAdd(&g_logits[rt + 8][ce + 1], accF[mt][nt][3]);
        }
    }
}

// ---------------------------------------------------------------------------
// router_finalize: logits + b2, softmax, shared/local split, top-2, outputs.
// ---------------------------------------------------------------------------
#define LGS 68
#define SMEM_RFIN (128 * LGS * 4 + 512)

__global__ void __launch_bounds__(256)
router_finalize_kernel(const float* __restrict__ b2, float* __restrict__ out) {
    extern __shared__ float rs[];
    float* lg   = rs;
    float* sinv = rs + 128 * LGS;

    const int tid = threadIdx.x;
    const int tok0 = blockIdx.x * 128;

#pragma unroll
    for (int hh = 0; hh < 8; hh++) {
        int f = tid + 256 * hh;
        int row = f >> 4;
        int c4 = (f & 15) * 4;
        float4 s = *reinterpret_cast<const float4*>(&g_logits[tok0 + row][c4]);
        float4 bb = *reinterpret_cast<const float4*>(&b2[c4]);
        s.x += bb.x; s.y += bb.y; s.z += bb.z; s.w += bb.w;
        *reinterpret_cast<float4*>(&lg[row * LGS + c4]) = s;
    }
    __syncthreads();

    if (tid < 128) {
        const int tok = tok0 + tid;
        float* row = &lg[tid * LGS];
        float mx = -1e30f;
#pragma unroll
        for (int e = 0; e < NEXP; e++) mx = fmaxf(mx, row[e]);
        float s = 0.f;
#pragma unroll
        for (int e = 0; e < NEXP; e++) {
            float ev = expf(row[e] - mx);
            row[e] = ev;
            s += ev;
        }
        float inv = 1.0f / s;
        sinv[tid] = inv;

        float v1 = -1.0f, v2 = -1.0f;
        int i1 = 0, i2v = 0;
#pragma unroll
        for (int e = NSHARED; e < NEXP; e++) {
            float v = row[e];
            if (v > v1)      { v2 = v1; i2v = i1; v1 = v; i1 = e; }
            else if (v > v2) { v2 = v;  i2v = e; }
        }
#pragma unroll
        for (int e = 0; e < NSHARED; e++)
            out[G_OFF + (size_t)tok * NSHARED + e] = row[e] * inv;
        out[LW_OFF + (size_t)tok * TOPK + 0] = v1 * inv;
        out[LW_OFF + (size_t)tok * TOPK + 1] = v2 * inv;
        out[LI_OFF + (size_t)tok * TOPK + 0] = (float)(i1 - NSHARED);
        out[LI_OFF + (size_t)tok * TOPK + 1] = (float)(i2v - NSHARED);
    }
    __syncthreads();

#pragma unroll
    for (int hh = 0; hh < 16; hh++) {
        int f = tid + 256 * hh;
        int tr = f >> 5;
        int ec = (f & 31) * 2;
        float inv = sinv[tr];
        float2 v = *reinterpret_cast<const float2*>(&lg[tr * LGS + ec]);
        v.x *= inv; v.y *= inv;
        *reinterpret_cast<float2*>(
            &out[W_OFF + (size_t)(tok0 + tr) * NEXP + ec]) = v;
    }
}

// ---------------------------------------------------------------------------
extern "C" void kernel_launch(void* const* d_in, const int* in_sizes, int n_in,
                              void* d_out, int out_size) {
    const float* x  = (const float*)d_in[0];
    const float* W1 = (const float*)d_in[1];
    const float* b1 = (const float*)d_in[2];
    const float* W2 = (const float*)d_in[3];
    const float* b2 = (const float*)d_in[4];
    float* out = (float*)d_out;

    static int attr_done = 0;
    if (!attr_done) {
        cudaFuncSetAttribute(gemm1_hmma_kernel,
                             cudaFuncAttributeMaxDynamicSharedMemorySize, SMEM_GEMM);
        cudaFuncSetAttribute(router_finalize_kernel,
                             cudaFuncAttributeMaxDynamicSharedMemorySize, SMEM_RFIN);
        attr_done = 1;
    }

    conv_x_kernel<<<(NTOK * DIN) / (256 * 4), 256>>>(x);
    conv_w1_kernel<<<dim3(HMID / 32, DIN / 32), dim3(32, 8)>>>(W1);
    conv_w2_kernel<<<dim3(NEXP / 32, HMID / 32), dim3(32, 8)>>>(W2);
    zero_logits_kernel<<<(NTOK * NEXP) / (256 * 4), 256>>>();
    gemm1_hmma_kernel<<<dim3(HMID / 128, NTOK / 128), 256, SMEM_GEMM>>>(b1);
    router_finalize_kernel<<<NTOK / 128, 256, SMEM_RFIN>>>(b2, out);
}

// round 16
// speedup vs baseline: 1.2905x; 1.0016x over previous
#include <cuda_runtime.h>
#include <cuda_fp16.h>
#include <math.h>
#include <stdint.h>

// ---------------------------------------------------------------------------
// Problem constants
// ---------------------------------------------------------------------------
#define NTOK  16384
#define DIN   2048
#define HMID  4096
#define NEXP  64
#define NSHARED 8
#define TOPK  2

// Output layout (flattened concat of the reference tuple)
#define G_OFF  0
#define LW_OFF (NTOK * NSHARED)
#define LI_OFF (LW_OFF + NTOK * TOPK)
#define W_OFF  (LI_OFF + NTOK * TOPK)

// ---------------------------------------------------------------------------
// Scratch (static device arrays; no allocation)
// ---------------------------------------------------------------------------
__device__ __half g_x0[(size_t)NTOK * DIN];           // x limb planes
__device__ __half g_x1[(size_t)NTOK * DIN];
__device__ __half g_w0[(size_t)HMID * DIN];           // W1^T limb planes
__device__ __half g_w1[(size_t)HMID * DIN];
__device__ __half g_u0[(size_t)NEXP * HMID];          // W2^T limb planes
__device__ __half g_u1[(size_t)NEXP * HMID];
__device__ float  g_logits[NTOK][NEXP];               // fused router logits

__device__ __forceinline__ uint32_t smem_u32(const void* p) {
    uint32_t a;
    asm("{ .reg .u64 t; cvta.to.shared.u64 t, %1; cvt.u32.u64 %0, t; }"
        : "=r"(a) : "l"(p));
    return a;
}

__device__ __forceinline__ float gelu_exact(float v) {
    return 0.5f * v * (1.0f + erff(v * 0.70710678118654752440f));
}

__device__ __forceinline__ void ldsm_x4(uint32_t* r, uint32_t addr) {
    asm volatile("ldmatrix.sync.aligned.m8n8.x4.shared.b16 {%0,%1,%2,%3}, [%4];"
                 : "=r"(r[0]), "=r"(r[1]), "=r"(r[2]), "=r"(r[3]) : "r"(addr));
}

__device__ __forceinline__ void mma16816(float* d, const uint32_t* a,
                                         uint32_t b0, uint32_t b1) {
    asm volatile(
        "mma.sync.aligned.m16n8k16.row.col.f32.f16.f16.f32 "
        "{%0,%1,%2,%3}, {%4,%5,%6,%7}, {%8,%9}, {%0,%1,%2,%3};"
        : "+f"(d[0]), "+f"(d[1]), "+f"(d[2]), "+f"(d[3])
        : "r"(a[0]), "r"(a[1]), "r"(a[2]), "r"(a[3]), "r"(b0), "r"(b1));
}

#define CP_ASYNC16(dst, src) \
    asm volatile("cp.async.cg.shared.global [%0], [%1], 16;" \
                 :: "r"(dst), "l"(src) : "memory")
#define CP_COMMIT() asm volatile("cp.async.commit_group;" ::: "memory")
#define BAR_SYNC(id, cnt) \
    asm volatile("bar.sync %0, %1;" :: "r"(id), "r"(cnt) : "memory")
#define BAR_ARRIVE(id, cnt) \
    asm volatile("bar.arrive %0, %1;" :: "r"(id), "r"(cnt) : "memory")

__device__ __forceinline__ uint32_t pack_limbs(float x, float y,
                                               float& rx, float& ry) {
    __half hx = __float2half_rn(x), hy = __float2half_rn(y);
    rx = x - __half2float(hx);
    ry = y - __half2float(hy);
    return (uint32_t)__half_as_ushort(hx) | ((uint32_t)__half_as_ushort(hy) << 16);
}

// ---------------------------------------------------------------------------
// prep_x: blocks [0, NXB): split x into 2 fp16 limb planes, 8 elems/thread.
//         blocks [NXB, NXB+NZB): zero g_logits.
// ---------------------------------------------------------------------------
#define NXB ((NTOK * DIN) / (256 * 8))        // 16384
#define NZB ((NTOK * NEXP) / (256 * 4))       // 1024

__global__ void __launch_bounds__(256)
prep_x_kernel(const float* __restrict__ x) {
    const int b = blockIdx.x;
    if (b < NXB) {
        size_t i = ((size_t)b * 256 + threadIdx.x) * 8;
#pragma unroll
        for (int half = 0; half < 2; half++) {
            size_t ii = i + half * 4;
            float4 v = *reinterpret_cast<const float4*>(&x[ii]);
            float a[4] = {v.x, v.y, v.z, v.w};
            unsigned short u0[4], u1[4];
#pragma unroll
            for (int j = 0; j < 4; j++) {
                __half h0 = __float2half_rn(a[j]);
                float r = a[j] - __half2float(h0);
                u0[j] = __half_as_ushort(h0);
                u1[j] = __half_as_ushort(__float2half_rn(r));
            }
            *reinterpret_cast<uint2*>(&g_x0[ii]) =
                make_uint2((uint32_t)u0[0] | ((uint32_t)u0[1] << 16),
                           (uint32_t)u0[2] | ((uint32_t)u0[3] << 16));
            *reinterpret_cast<uint2*>(&g_x1[ii]) =
                make_uint2((uint32_t)u1[0] | ((uint32_t)u1[1] << 16),
                           (uint32_t)u1[2] | ((uint32_t)u1[3] << 16));
        }
    } else {
        size_t i = ((size_t)(b - NXB) * 256 + threadIdx.x) * 4;
        *reinterpret_cast<float4*>(&g_logits[0][0] + i) =
            make_float4(0.f, 0.f, 0.f, 0.f);
    }
}

// ---------------------------------------------------------------------------
// conv_w1: transpose W1 [K,N] -> [N,K], split into 2 fp16 limb planes
// ---------------------------------------------------------------------------
__global__ void __launch_bounds__(256)
conv_w1_kernel(const float* __restrict__ W1) {
    __shared__ float tile[32][33];
    const int tx = threadIdx.x, ty = threadIdx.y;
    const int n0 = blockIdx.x * 32;
    const int k0 = blockIdx.y * 32;
#pragma unroll
    for (int j = 0; j < 4; j++)
        tile[ty + j * 8][tx] = W1[(size_t)(k0 + ty + j * 8) * HMID + n0 + tx];
    __syncthreads();
#pragma unroll
    for (int j = 0; j < 4; j++) {
        float v = tile[tx][ty + j * 8];
        __half h0 = __float2half_rn(v);
        float r = v - __half2float(h0);
        size_t o = (size_t)(n0 + ty + j * 8) * DIN + k0 + tx;
        g_w0[o] = h0;
        g_w1[o] = __float2half_rn(r);
    }
}

// ---------------------------------------------------------------------------
// conv_w2: transpose W2 [K=4096, 64] -> [64][4096], split into 2 limb planes
// ---------------------------------------------------------------------------
__global__ void __launch_bounds__(256)
conv_w2_kernel(const float* __restrict__ W2) {
    __shared__ float tile[32][33];
    const int tx = threadIdx.x, ty = threadIdx.y;
    const int n0 = blockIdx.x * 32;
    const int k0 = blockIdx.y * 32;
#pragma unroll
    for (int j = 0; j < 4; j++)
        tile[ty + j * 8][tx] = W2[(size_t)(k0 + ty + j * 8) * NEXP + n0 + tx];
    __syncthreads();
#pragma unroll
    for (int j = 0; j < 4; j++) {
        float v = tile[tx][ty + j * 8];
        __half h0 = __float2half_rn(v);
        float r = v - __half2float(h0);
        size_t o = (size_t)(n0 + ty + j * 8) * HMID + k0 + tx;
        g_u0[o] = h0;
        g_u1[o] = __float2half_rn(r);
    }
}

// ---------------------------------------------------------------------------
// gemm1 + fused router partial (R15 winner, unchanged):
//   mainloop: h = x @ W1 (fp16 2-limb, 3 products), named-barrier pipeline
//   epilogue: bias+gelu -> h limbs staged in smem; W2^T K-slice; 3-product
//             HMMA 128 tok x 64 exp x K=128; atomicAdd into g_logits.
// ---------------------------------------------------------------------------
#define TILE64  (128 * 64)
#define STAGE64 (4 * TILE64)
#define GSTAGES 3
#define SMEM_GEMM (GSTAGES * STAGE64)  // 98304
#define KT (DIN / 32)                  // 64
#define H0_OFF 0
#define H1_OFF 32768
#define U0_OFF 65536
#define U1_OFF 81920

__global__ void __launch_bounds__(256, 2)
gemm1_hmma_kernel(const float* __restrict__ b1) {
    extern __shared__ char smem[];
    const uint32_t sbase = smem_u32(smem);
    const int tid = threadIdx.x;
    const int wid = tid >> 5;
    const int lid = tid & 31;
    const int row0 = blockIdx.y * 128;
    const int col0 = blockIdx.x * 128;
    const int wm = (wid >> 2) * 64;
    const int wn = (wid & 3) * 32;

    const int lr = tid >> 1;
    const int cc = (tid & 1) * 2;
    const int mS = (lr >> 1) & 3;
    const uint32_t dst0 = (uint32_t)lr * 64 + (uint32_t)(((cc)     ^ mS) << 4);
    const uint32_t dst1 = (uint32_t)lr * 64 + (uint32_t)(((cc + 1) ^ mS) << 4);
    const char* gA0 = (const char*)(g_x0 + (size_t)(row0 + lr) * DIN) + cc * 16;
    const char* gA1 = (const char*)(g_x1 + (size_t)(row0 + lr) * DIN) + cc * 16;
    const char* gB0 = (const char*)(g_w0 + (size_t)(col0 + lr) * DIN) + cc * 16;
    const char* gB1 = (const char*)(g_w1 + (size_t)(col0 + lr) * DIN) + cc * 16;

    float acc[4][4][4];
#pragma unroll
    for (int i = 0; i < 4; i++)
#pragma unroll
        for (int j = 0; j < 4; j++)
#pragma unroll
            for (int k = 0; k < 4; k++) acc[i][j][k] = 0.f;

    auto load_stage = [&](int s, int kt) {
        const uint32_t sb = sbase + s * STAGE64;
        const int go = kt * 64;
        CP_ASYNC16(sb + dst0,              gA0 + go);
        CP_ASYNC16(sb + dst1,              gA0 + go + 16);
        CP_ASYNC16(sb + TILE64 + dst0,     gA1 + go);
        CP_ASYNC16(sb + TILE64 + dst1,     gA1 + go + 16);
        CP_ASYNC16(sb + 2 * TILE64 + dst0, gB0 + go);
        CP_ASYNC16(sb + 2 * TILE64 + dst1, gB0 + go + 16);
        CP_ASYNC16(sb + 3 * TILE64 + dst0, gB1 + go);
        CP_ASYNC16(sb + 3 * TILE64 + dst1, gB1 + go + 16);
        CP_COMMIT();
    };

    const uint32_t aRowB = (uint32_t)(wm + (lid & 15)) * 64;
    const int cidxA = lid >> 4;
    const int mA = ((lid & 15) >> 1) & 3;
    const int brow = (lid & 7) + ((lid >> 4) & 1) * 8;
    const uint32_t bRowB = (uint32_t)(wn + brow) * 64;
    const int cidxB = (lid >> 3) & 1;
    const int mB = (brow >> 1) & 3;
    uint32_t aCol[2], bCol[2];
#pragma unroll
    for (int k16 = 0; k16 < 2; k16++) {
        aCol[k16] = (uint32_t)((((k16 << 1) | cidxA) ^ mA) << 4);
        bCol[k16] = (uint32_t)((((k16 << 1) | cidxB) ^ mB) << 4);
    }

    // prologue: stages 0,1 in flight; post ready[0] ONLY
    load_stage(0, 0);
    load_stage(1, 1);
    asm volatile("cp.async.wait_group 1;" ::: "memory");
    BAR_ARRIVE(1 + 0, 512);

    int r0 = 0, r1 = 1, r2 = 2;

    for (int kt = 0; kt < KT; kt++) {
        BAR_SYNC(1 + r0, 512);

        const uint32_t sb = sbase + r0 * STAGE64;

        // ================= k16 = 0 =================
        {
            uint32_t b0[2][4], b1f[2][4];
#pragma unroll
            for (int nt2 = 0; nt2 < 2; nt2++) {
                const uint32_t bo = bRowB + nt2 * 1024 + bCol[0];
                ldsm_x4(b0[nt2],  sb + 2 * TILE64 + bo);
                ldsm_x4(b1f[nt2], sb + 3 * TILE64 + bo);
            }
            uint32_t a0[4][4], a1[4][4];
#pragma unroll
            for (int mt = 0; mt < 4; mt++)
                ldsm_x4(a0[mt], sb + aRowB + mt * 1024 + aCol[0]);
#pragma unroll
            for (int mt = 0; mt < 4; mt++)
                ldsm_x4(a1[mt], sb + TILE64 + aRowB + mt * 1024 + aCol[0]);

#pragma unroll
            for (int mt = 0; mt < 4; mt++)
#pragma unroll
                for (int nt = 0; nt < 4; nt++) {
                    const int n2 = nt >> 1, h = (nt & 1) * 2;
                    mma16816(acc[mt][nt], a0[mt], b0[n2][h], b0[n2][h + 1]);
                }
#pragma unroll
            for (int mt = 0; mt < 4; mt++)
#pragma unroll
                for (int nt = 0; nt < 4; nt++) {
                    const int n2 = nt >> 1, h = (nt & 1) * 2;
                    mma16816(acc[mt][nt], a0[mt], b1f[n2][h], b1f[n2][h + 1]);
                }
#pragma unroll
            for (int mt = 0; mt < 4; mt++)
#pragma unroll
                for (int nt = 0; nt < 4; nt++) {
                    const int n2 = nt >> 1, h = (nt & 1) * 2;
                    mma16816(acc[mt][nt], a1[mt], b0[n2][h], b0[n2][h + 1]);
                }
        }

        // ================= k16 = 1 =================
        {
            uint32_t b0[2][4], b1f[2][4];
#pragma unroll
            for (int nt2 = 0; nt2 < 2; nt2++) {
                const uint32_t bo = bRowB + nt2 * 1024 + bCol[1];
                ldsm_x4(b0[nt2],  sb + 2 * TILE64 + bo);
                ldsm_x4(b1f[nt2], sb + 3 * TILE64 + bo);
            }
            uint32_t a0[4][4], a1[4][4];
#pragma unroll
            for (int mt = 0; mt < 4; mt++)
                ldsm_x4(a0[mt], sb + aRowB + mt * 1024 + aCol[1]);
#pragma unroll
            for (int mt = 0; mt < 4; mt++)
                ldsm_x4(a1[mt], sb + TILE64 + aRowB + mt * 1024 + aCol[1]);

            if (kt + 3 < KT) BAR_ARRIVE(4 + r0, 512);
            if (kt >= 1 && kt + 2 < KT) BAR_SYNC(4 + r2, 512);
            if (kt + 2 < KT) load_stage(r2, kt + 2);

#pragma unroll
            for (int mt = 0; mt < 4; mt++)
#pragma unroll
                for (int nt = 0; nt < 4; nt++) {
                    const int n2 = nt >> 1, h = (nt & 1) * 2;
                    mma16816(acc[mt][nt], a0[mt], b0[n2][h], b0[n2][h + 1]);
                }

            if (kt + 1 < KT) {
                if (kt + 2 < KT) {
                    asm volatile("cp.async.wait_group 1;" ::: "memory");
                } else {
                    asm volatile("cp.async.wait_group 0;" ::: "memory");
                }
                BAR_ARRIVE(1 + r1, 512);
            }

#pragma unroll
            for (int mt = 0; mt < 4; mt++)
#pragma unroll
                for (int nt = 0; nt < 4; nt++) {
                    const int n2 = nt >> 1, h = (nt & 1) * 2;
                    mma16816(acc[mt][nt], a0[mt], b1f[n2][h], b1f[n2][h + 1]);
                }
#pragma unroll
            for (int mt = 0; mt < 4; mt++)
#pragma unroll
                for (int nt = 0; nt < 4; nt++) {
                    const int n2 = nt >> 1, h = (nt & 1) * 2;
                    mma16816(acc[mt][nt], a1[mt], b0[n2][h], b0[n2][h + 1]);
                }
        }

        const int t = r0; r0 = r1; r1 = r2; r2 = t;
    }

    // =========================== fused epilogue ===========================
    __syncthreads();   // all pipeline smem reads complete

    // prefetch W2^T limb K-slices: [64 exp][128 k], 256B rows, swizzled
    {
        const int ue = tid >> 2;
        const int c0 = (tid & 3) * 4;
        const char* gu0 = (const char*)(g_u0 + (size_t)ue * HMID + col0);
        const char* gu1 = (const char*)(g_u1 + (size_t)ue * HMID + col0);
#pragma unroll
        for (int c = 0; c < 4; c++) {
            int ch = c0 + c;
            uint32_t d = (uint32_t)ue * 256 + (uint32_t)((ch ^ (ue & 15)) << 4);
            CP_ASYNC16(sbase + U0_OFF + d, gu0 + ch * 16);
            CP_ASYNC16(sbase + U1_OFF + d, gu1 + ch * 16);
        }
        CP_COMMIT();
    }

    // bias + gelu + split h into fp16 limbs staged in smem
    const int g = lid >> 2;
    const int i2 = (lid & 3) * 2;
#pragma unroll
    for (int nt = 0; nt < 4; nt++) {
        const int col = wn + nt * 8 + i2;           // kcol within tile
        const float bx = b1[col0 + col], by = b1[col0 + col + 1];
        const uint32_t chunkOff = (uint32_t)((col & 7) * 2);
        const uint32_t chunkIdx = (uint32_t)(col >> 3);
#pragma unroll
        for (int mt = 0; mt < 4; mt++) {
            const int rowL = wm + mt * 16 + g;
            const int rowH = rowL + 8;
            float lox = gelu_exact(acc[mt][nt][0] + bx);
            float loy = gelu_exact(acc[mt][nt][1] + by);
            float hix = gelu_exact(acc[mt][nt][2] + bx);
            float hiy = gelu_exact(acc[mt][nt][3] + by);
            float r0f, r1f, r2f, r3f;
            uint32_t p0 = pack_limbs(lox, loy, r0f, r1f);
            uint32_t p1 = pack_limbs(hix, hiy, r2f, r3f);
            uint32_t q0 = (uint32_t)__half_as_ushort(__float2half_rn(r0f)) |
                          ((uint32_t)__half_as_ushort(__float2half_rn(r1f)) << 16);
            uint32_t q1 = (uint32_t)__half_as_ushort(__float2half_rn(r2f)) |
                          ((uint32_t)__half_as_ushort(__float2half_rn(r3f)) << 16);
            uint32_t stL = (uint32_t)rowL * 256 +
                           ((chunkIdx ^ (uint32_t)(rowL & 15)) << 4) + chunkOff;
            uint32_t stH = (uint32_t)rowH * 256 +
                           ((chunkIdx ^ (uint32_t)(rowH & 15)) << 4) + chunkOff;
            *reinterpret_cast<uint32_t*>(smem + H0_OFF + stL) = p0;
            *reinterpret_cast<uint32_t*>(smem + H0_OFF + stH) = p1;
            *reinterpret_cast<uint32_t*>(smem + H1_OFF + stL) = q0;
            *reinterpret_cast<uint32_t*>(smem + H1_OFF + stH) = q1;
        }
    }
    asm volatile("cp.async.wait_group 0;" ::: "memory");
    __syncthreads();

    // fused MMA: 128 tokens x 64 experts, K = 128 (this CTA's col slice)
    const int wmF = (wid >> 1) * 32;
    const int wnF = (wid & 1) * 32;
    const int aRowM = lid & 15;
    float accF[2][4][4];
#pragma unroll
    for (int i = 0; i < 2; i++)
#pragma unroll
        for (int j = 0; j < 4; j++)
#pragma unroll
            for (int k = 0; k < 4; k++) accF[i][j][k] = 0.f;

#pragma unroll
    for (int k16 = 0; k16 < 8; k16++) {
        uint32_t b0[2][4], b1f[2][4];
#pragma unroll
        for (int nt2 = 0; nt2 < 2; nt2++) {
            const uint32_t rb = (uint32_t)(wnF + nt2 * 16 + brow) * 256 +
                                (uint32_t)(((k16 * 2 + cidxB) ^ brow) << 4);
            ldsm_x4(b0[nt2],  sbase + U0_OFF + rb);
            ldsm_x4(b1f[nt2], sbase + U1_OFF + rb);
        }
        uint32_t a0[2][4], a1[2][4];
#pragma unroll
        for (int mt = 0; mt < 2; mt++) {
            const uint32_t ra = (uint32_t)(wmF + mt * 16 + aRowM) * 256 +
                                (uint32_t)(((k16 * 2 + cidxA) ^ aRowM) << 4);
            ldsm_x4(a0[mt], sbase + H0_OFF + ra);
            ldsm_x4(a1[mt], sbase + H1_OFF + ra);
        }
#pragma unroll
        for (int mt = 0; mt < 2; mt++)
#pragma unroll
            for (int nt = 0; nt < 4; nt++) {
                const int n2 = nt >> 1, h = (nt & 1) * 2;
                mma16816(accF[mt][nt], a0[mt], b0[n2][h], b0[n2][h + 1]);
            }
#pragma unroll
        for (int mt = 0; mt < 2; mt++)
#pragma unroll
            for (int nt = 0; nt < 4; nt++) {
                const int n2 = nt >> 1, h = (nt & 1) * 2;
                mma16816(accF[mt][nt], a0[mt], b1f[n2][h], b1f[n2][h + 1]);
            }
#pragma unroll
        for (int mt = 0; mt < 2; mt++)
#pragma unroll
            for (int nt = 0; nt < 4; nt++) {
                const int n2 = nt >> 1, h = (nt & 1) * 2;
                mma16816(accF[mt][nt], a1[mt], b0[n2][h], b0[n2][h + 1]);
            }
    }

    // accumulate partial logits
#pragma unroll
    for (int nt = 0; nt < 4; nt++) {
        const int ce = wnF + nt * 8 + i2;
#pragma unroll
        for (int mt = 0; mt < 2; mt++) {
            const int rt = row0 + wmF + mt * 16 + g;
            atomicAdd(&g_logits[rt][ce],         accF[mt][nt][0]);
            atomicAdd(&g_logits[rt][ce + 1],     accF[mt][nt][1]);
            atomicAdd(&g_logits[rt + 8][ce],     accF[mt][nt][2]);
            atomicAdd(&g_logits[rt + 8][ce + 1], accF[mt][nt][3]);
        }
    }
}

// ---------------------------------------------------------------------------
// router_finalize: logits + b2, softmax, shared/local split, top-2, outputs.
// ---------------------------------------------------------------------------
#define LGS 68
#define SMEM_RFIN (128 * LGS * 4 + 512)

__global__ void __launch_bounds__(256)
router_finalize_kernel(const float* __restrict__ b2, float* __restrict__ out) {
    extern __shared__ float rs[];
    float* lg   = rs;
    float* sinv = rs + 128 * LGS;

    const int tid = threadIdx.x;
    const int tok0 = blockIdx.x * 128;

#pragma unroll
    for (int hh = 0; hh < 8; hh++) {
        int f = tid + 256 * hh;
        int row = f >> 4;
        int c4 = (f & 15) * 4;
        float4 s = *reinterpret_cast<const float4*>(&g_logits[tok0 + row][c4]);
        float4 bb = *reinterpret_cast<const float4*>(&b2[c4]);
        s.x += bb.x; s.y += bb.y; s.z += bb.z; s.w += bb.w;
        *reinterpret_cast<float4*>(&lg[row * LGS + c4]) = s;
    }
    __syncthreads();

    if (tid < 128) {
        const int tok = tok0 + tid;
        float* row = &lg[tid * LGS];
        float mx = -1e30f;
#pragma unroll
        for (int e = 0; e < NEXP; e++) mx = fmaxf(mx, row[e]);
        float s = 0.f;
#pragma unroll
        for (int e = 0; e < NEXP; e++) {
            float ev = expf(row[e] - mx);
            row[e] = ev;
            s += ev;
        }
        float inv = 1.0f / s;
        sinv[tid] = inv;

        float v1 = -1.0f, v2 = -1.0f;
        int i1 = 0, i2v = 0;
#pragma unroll
        for (int e = NSHARED; e < NEXP; e++) {
            float v = row[e];
            if (v > v1)      { v2 = v1; i2v = i1; v1 = v; i1 = e; }
            else if (v > v2) { v2 = v;  i2v = e; }
        }
#pragma unroll
        for (int e = 0; e < NSHARED; e++)
            out[G_OFF + (size_t)tok * NSHARED + e] = row[e] * inv;
        out[LW_OFF + (size_t)tok * TOPK + 0] = v1 * inv;
        out[LW_OFF + (size_t)tok * TOPK + 1] = v2 * inv;
        out[LI_OFF + (size_t)tok * TOPK + 0] = (float)(i1 - NSHARED);
        out[LI_OFF + (size_t)tok * TOPK + 1] = (float)(i2v - NSHARED);
    }
    __syncthreads();

#pragma unroll
    for (int hh = 0; hh < 16; hh++) {
        int f = tid + 256 * hh;
        int tr = f >> 5;
        int ec = (f & 31) * 2;
        float inv = sinv[tr];
        float2 v = *reinterpret_cast<const float2*>(&lg[tr * LGS + ec]);
        v.x *= inv; v.y *= inv;
        *reinterpret_cast<float2*>(
            &out[W_OFF + (size_t)(tok0 + tr) * NEXP + ec]) = v;
    }
}

// ---------------------------------------------------------------------------
extern "C" void kernel_launch(void* const* d_in, const int* in_sizes, int n_in,
                              void* d_out, int out_size) {
    const float* x  = (const float*)d_in[0];
    const float* W1 = (const float*)d_in[1];
    const float* b1 = (const float*)d_in[2];
    const float* W2 = (const float*)d_in[3];
    const float* b2 = (const float*)d_in[4];
    float* out = (float*)d_out;

    static int attr_done = 0;
    if (!attr_done) {
        cudaFuncSetAttribute(gemm1_hmma_kernel,
                             cudaFuncAttributeMaxDynamicSharedMemorySize, SMEM_GEMM);
        cudaFuncSetAttribute(router_finalize_kernel,
                             cudaFuncAttributeMaxDynamicSharedMemorySize, SMEM_RFIN);
        attr_done = 1;
    }

    prep_x_kernel<<<NXB + NZB, 256>>>(x);
    conv_w1_kernel<<<dim3(HMID / 32, DIN / 32), dim3(32, 8)>>>(W1);
    conv_w2_kernel<<<dim3(NEXP / 32, HMID / 32), dim3(32, 8)>>>(W2);
    gemm1_hmma_kernel<<<dim3(HMID / 128, NTOK / 128), 256, SMEM_GEMM>>>(b1);
    router_finalize_kernel<<<NTOK / 128, 256, SMEM_RFIN>>>(b2, out);
}